// round 8
// baseline (speedup 1.0000x reference)
#include <cuda_runtime.h>
#include <cstdint>

#define NN 100000
#define EE 600000
#define HH 128
#define GG 1000
#define BN_EPS 1e-5f
#define NB_SCAN 98   // ceil(NN/1024)

// ---- scratch (alloc-free: __device__ globals) ----
__device__ float g_h0[NN * HH];    // feature ping-pong buffer 0
__device__ float g_h1[NN * HH];    // feature ping-pong buffer 1
__device__ float g_t3[NN * 3];     // layer-0 pre-MLP (3 feats)
// CSR scratch
__device__ int g_deg[NN];
__device__ int g_rowptr[NN + 1];
__device__ int g_cursor[NN];
__device__ int g_bsum[128];
__device__ int g_csr[EE];

__device__ __forceinline__ float* hbuf(int id) { return id == 0 ? g_h0 : g_h1; }

// smem layout (floats)
#define US_STRIDE 132
#define AS_STRIDE 36
#define WS_STRIDE 136
#define US_OFF 0
#define AS_OFF (128 * US_STRIDE)
#define WS_OFF (AS_OFF + 128 * AS_STRIDE)
#define SMEM_FLOATS (WS_OFF + 32 * WS_STRIDE)
#define SMEM_BYTES (SMEM_FLOATS * 4)

__device__ __forceinline__ uint32_t f2tf32(float f) {
    uint32_t o;
    asm("cvt.rna.tf32.f32 %0, %1;" : "=r"(o) : "f"(f));
    return o;
}

// ================= CSR build =================
__global__ void k_zero_deg() {
    int i = blockIdx.x * blockDim.x + threadIdx.x;
    if (i < NN) g_deg[i] = 0;
}

__global__ void k_hist(const int* __restrict__ ei) {
    int e = blockIdx.x * blockDim.x + threadIdx.x;
    if (e < EE) atomicAdd(&g_deg[ei[EE + e]], 1);
}

__global__ __launch_bounds__(1024) void k_scan1() {
    __shared__ int s[1024];
    int tid = threadIdx.x;
    int i = blockIdx.x * 1024 + tid;
    int v = (i < NN) ? g_deg[i] : 0;
    s[tid] = v;
    __syncthreads();
#pragma unroll
    for (int off = 1; off < 1024; off <<= 1) {
        int t = (tid >= off) ? s[tid - off] : 0;
        __syncthreads();
        s[tid] += t;
        __syncthreads();
    }
    if (i < NN) g_rowptr[i] = s[tid] - v;
    if (tid == 1023) g_bsum[blockIdx.x] = s[1023];
}

__global__ void k_scan2() {
    __shared__ int s[128];
    int tid = threadIdx.x;
    int v = (tid < NB_SCAN) ? g_bsum[tid] : 0;
    s[tid] = v;
    __syncthreads();
#pragma unroll
    for (int off = 1; off < 128; off <<= 1) {
        int t = (tid >= off) ? s[tid - off] : 0;
        __syncthreads();
        s[tid] += t;
        __syncthreads();
    }
    if (tid < NB_SCAN) g_bsum[tid] = s[tid] - v;
}

__global__ void k_scan3() {
    int i = blockIdx.x * blockDim.x + threadIdx.x;
    if (i < NN) {
        int r = g_rowptr[i] + g_bsum[i >> 10];
        g_rowptr[i] = r;
        g_cursor[i] = r;
    }
    if (i == 0) g_rowptr[NN] = EE;
}

__global__ void k_reorder(const int* __restrict__ ei) {
    int e = blockIdx.x * blockDim.x + threadIdx.x;
    if (e >= EE) return;
    int s = ei[e];
    int d = ei[EE + e];
    int pos = atomicAdd(&g_cursor[d], 1);
    g_csr[pos] = s;
}

// ================= layer-0 gather (3 feats) =================
__global__ void k_gather3(const float* __restrict__ x) {
    int n = blockIdx.x * blockDim.x + threadIdx.x;
    if (n >= NN) return;
    int beg = g_rowptr[n], end = g_rowptr[n + 1];
    float a0 = x[n * 3 + 0], a1 = x[n * 3 + 1], a2 = x[n * 3 + 2];
    for (int p = beg; p < end; p++) {
        int s = g_csr[p];
        a0 += x[s * 3 + 0];
        a1 += x[s * 3 + 1];
        a2 += x[s * 3 + 2];
    }
    g_t3[n * 3 + 0] = a0;
    g_t3[n * 3 + 1] = a1;
    g_t3[n * 3 + 2] = a2;
}

// ================= out init =================
__global__ void k_init_out(const float* __restrict__ bc, float* __restrict__ out) {
    int g = blockIdx.x * blockDim.x + threadIdx.x;
    if (g < GG) out[g] = bc[0];
}

// ================= fused layer =================
// layers 1-4: gather (CSR, reads hbuf[hsrc]) -> Us, stage1 MMA -> Us, stage2 -> hbuf[hdst]
// layer 0:    tiny 3->128 MLP from g_t3 -> Us, stage2 -> hbuf[hdst]
// last layer: epilogue reduces ReLU(h)@Wc into out[batch[row]] (no feature store)
__global__ __launch_bounds__(256, 2) void k_fused(
    int layer0, int last, int hsrc, int hdst,
    const float* __restrict__ W1, const float* __restrict__ b1,
    const float* __restrict__ gam, const float* __restrict__ bet,
    const float* __restrict__ mu, const float* __restrict__ var,
    const float* __restrict__ W2, const float* __restrict__ b2,
    const int* __restrict__ batch, const float* __restrict__ Wc,
    float* __restrict__ out) {
    extern __shared__ float smem[];
    float* Us = smem + US_OFF;
    float* As = smem + AS_OFF;   // layer0 params / last-layer rowdot
    float* Ws = smem + WS_OFF;
    const float* Hs = hbuf(hsrc);
    float* Hd = hbuf(hdst);

    int tid = threadIdx.x;
    int warp = tid >> 5, lane = tid & 31;
    int wm = warp & 3;
    int wn = warp >> 2;
    int gq = lane >> 2;
    int tg = lane & 3;
    int row0 = blockIdx.x * 128;

    // ---- stage 1 ----
    if (layer0) {
        float* W1s = As;
        float* sc = As + 384;
        float* sh = As + 512;
        for (int i = tid; i < 384; i += 256) W1s[i] = W1[i];
        if (tid < 128) {
            float s = gam[tid] * rsqrtf(var[tid] + BN_EPS);
            sc[tid] = s;
            sh[tid] = bet[tid] + (b1[tid] - mu[tid]) * s;
        }
        __syncthreads();
#pragma unroll 4
        for (int i = 0; i < 64; i++) {
            int idx = tid + i * 256;
            int r = idx >> 7, c = idx & 127;
            int row = row0 + r;
            float x0 = 0.f, x1 = 0.f, x2 = 0.f;
            if (row < NN) {
                x0 = g_t3[row * 3 + 0];
                x1 = g_t3[row * 3 + 1];
                x2 = g_t3[row * 3 + 2];
            }
            float u = x0 * W1s[c] + x1 * W1s[128 + c] + x2 * W1s[256 + c];
            u = fmaxf(u * sc[c] + sh[c], 0.f);
            Us[r * US_STRIDE + c] = __uint_as_float(f2tf32(u));
        }
        __syncthreads();
    } else {
        // ---- fused CSR gather into Us (tf32); reads Hs only (no alias w/ Hd) ----
#pragma unroll 1
        for (int i = 0; i < 16; i++) {
            int r = warp * 16 + i;
            int row = row0 + r;
            float4 acc = make_float4(0.f, 0.f, 0.f, 0.f);
            if (row < NN) {
                acc = *((const float4*)&Hs[row * HH + lane * 4]);
                int beg = g_rowptr[row], end = g_rowptr[row + 1];
                int p = beg;
                for (; p + 1 < end; p += 2) {
                    int s0 = g_csr[p], s1 = g_csr[p + 1];
                    float4 v0 = *((const float4*)&Hs[s0 * HH + lane * 4]);
                    float4 v1 = *((const float4*)&Hs[s1 * HH + lane * 4]);
                    acc.x += v0.x + v1.x;
                    acc.y += v0.y + v1.y;
                    acc.z += v0.z + v1.z;
                    acc.w += v0.w + v1.w;
                }
                if (p < end) {
                    int s0 = g_csr[p];
                    float4 v0 = *((const float4*)&Hs[s0 * HH + lane * 4]);
                    acc.x += v0.x;
                    acc.y += v0.y;
                    acc.z += v0.z;
                    acc.w += v0.w;
                }
            }
            Us[r * US_STRIDE + lane * 4 + 0] = __uint_as_float(f2tf32(acc.x));
            Us[r * US_STRIDE + lane * 4 + 1] = __uint_as_float(f2tf32(acc.y));
            Us[r * US_STRIDE + lane * 4 + 2] = __uint_as_float(f2tf32(acc.z));
            Us[r * US_STRIDE + lane * 4 + 3] = __uint_as_float(f2tf32(acc.w));
        }
        __syncthreads();

        // ---- stage 1 MMA: u = ReLU(BN(Us@W1+b1)) ----
        float c1[2][8][4];
#pragma unroll
        for (int mt = 0; mt < 2; mt++)
#pragma unroll
            for (int nt = 0; nt < 8; nt++)
#pragma unroll
                for (int r = 0; r < 4; r++) c1[mt][nt][r] = 0.f;

        for (int kc = 0; kc < 4; kc++) {
#pragma unroll
            for (int i = 0; i < 4; i++) {
                int idx = tid + i * 256;
                int k = idx >> 5;
                int q = idx & 31;
                float4 v = *((const float4*)&W1[(kc * 32 + k) * 128 + q * 4]);
                Ws[k * WS_STRIDE + q * 4 + 0] = __uint_as_float(f2tf32(v.x));
                Ws[k * WS_STRIDE + q * 4 + 1] = __uint_as_float(f2tf32(v.y));
                Ws[k * WS_STRIDE + q * 4 + 2] = __uint_as_float(f2tf32(v.z));
                Ws[k * WS_STRIDE + q * 4 + 3] = __uint_as_float(f2tf32(v.w));
            }
            __syncthreads();
#pragma unroll
            for (int ks = 0; ks < 4; ks++) {
                int k0 = ks * 8;
                int kcol = kc * 32 + k0;
                uint32_t a[2][4];
#pragma unroll
                for (int mt = 0; mt < 2; mt++) {
                    int rb = wm * 32 + mt * 16;
                    a[mt][0] = __float_as_uint(Us[(rb + gq) * US_STRIDE + kcol + tg]);
                    a[mt][1] = __float_as_uint(Us[(rb + gq + 8) * US_STRIDE + kcol + tg]);
                    a[mt][2] = __float_as_uint(Us[(rb + gq) * US_STRIDE + kcol + tg + 4]);
                    a[mt][3] = __float_as_uint(Us[(rb + gq + 8) * US_STRIDE + kcol + tg + 4]);
                }
                uint32_t b[8][2];
#pragma unroll
                for (int nt = 0; nt < 8; nt++) {
                    int col = wn * 64 + nt * 8 + gq;
                    b[nt][0] = __float_as_uint(Ws[(k0 + tg) * WS_STRIDE + col]);
                    b[nt][1] = __float_as_uint(Ws[(k0 + 4 + tg) * WS_STRIDE + col]);
                }
#pragma unroll
                for (int mt = 0; mt < 2; mt++)
#pragma unroll
                    for (int nt = 0; nt < 8; nt++) {
                        asm volatile(
                            "mma.sync.aligned.m16n8k8.row.col.f32.tf32.tf32.f32 "
                            "{%0,%1,%2,%3}, {%4,%5,%6,%7}, {%8,%9}, {%0,%1,%2,%3};"
                            : "+f"(c1[mt][nt][0]), "+f"(c1[mt][nt][1]),
                              "+f"(c1[mt][nt][2]), "+f"(c1[mt][nt][3])
                            : "r"(a[mt][0]), "r"(a[mt][1]), "r"(a[mt][2]), "r"(a[mt][3]),
                              "r"(b[nt][0]), "r"(b[nt][1]));
                    }
            }
            __syncthreads();
        }

        // BN + ReLU -> Us in place (all stage-1 reads complete)
#pragma unroll
        for (int nt = 0; nt < 8; nt++) {
            int col = wn * 64 + nt * 8 + tg * 2;
            float s0 = gam[col] * rsqrtf(var[col] + BN_EPS);
            float s1 = gam[col + 1] * rsqrtf(var[col + 1] + BN_EPS);
            float sh0 = bet[col] + (b1[col] - mu[col]) * s0;
            float sh1 = bet[col + 1] + (b1[col + 1] - mu[col + 1]) * s1;
#pragma unroll
            for (int mt = 0; mt < 2; mt++) {
                int rb = wm * 32 + mt * 16 + gq;
#pragma unroll
                for (int half = 0; half < 2; half++) {
                    int r = rb + half * 8;
                    float v0 = fmaxf(c1[mt][nt][half * 2 + 0] * s0 + sh0, 0.f);
                    float v1 = fmaxf(c1[mt][nt][half * 2 + 1] * s1 + sh1, 0.f);
                    Us[r * US_STRIDE + col] = __uint_as_float(f2tf32(v0));
                    Us[r * US_STRIDE + col + 1] = __uint_as_float(f2tf32(v1));
                }
            }
        }
        __syncthreads();
    }

    // ---- stage 2: h = ReLU(Us @ W2 + b2) ----
    float c2[2][8][4];
#pragma unroll
    for (int mt = 0; mt < 2; mt++)
#pragma unroll
        for (int nt = 0; nt < 8; nt++)
#pragma unroll
            for (int r = 0; r < 4; r++) c2[mt][nt][r] = 0.f;

    for (int kc = 0; kc < 4; kc++) {
#pragma unroll
        for (int i = 0; i < 4; i++) {
            int idx = tid + i * 256;
            int k = idx >> 5;
            int q = idx & 31;
            float4 v = *((const float4*)&W2[(kc * 32 + k) * 128 + q * 4]);
            Ws[k * WS_STRIDE + q * 4 + 0] = __uint_as_float(f2tf32(v.x));
            Ws[k * WS_STRIDE + q * 4 + 1] = __uint_as_float(f2tf32(v.y));
            Ws[k * WS_STRIDE + q * 4 + 2] = __uint_as_float(f2tf32(v.z));
            Ws[k * WS_STRIDE + q * 4 + 3] = __uint_as_float(f2tf32(v.w));
        }
        __syncthreads();
#pragma unroll
        for (int ks = 0; ks < 4; ks++) {
            int k0 = ks * 8;
            int kcol = kc * 32 + k0;
            uint32_t a[2][4];
#pragma unroll
            for (int mt = 0; mt < 2; mt++) {
                int rb = wm * 32 + mt * 16;
                a[mt][0] = __float_as_uint(Us[(rb + gq) * US_STRIDE + kcol + tg]);
                a[mt][1] = __float_as_uint(Us[(rb + gq + 8) * US_STRIDE + kcol + tg]);
                a[mt][2] = __float_as_uint(Us[(rb + gq) * US_STRIDE + kcol + tg + 4]);
                a[mt][3] = __float_as_uint(Us[(rb + gq + 8) * US_STRIDE + kcol + tg + 4]);
            }
            uint32_t b[8][2];
#pragma unroll
            for (int nt = 0; nt < 8; nt++) {
                int col = wn * 64 + nt * 8 + gq;
                b[nt][0] = __float_as_uint(Ws[(k0 + tg) * WS_STRIDE + col]);
                b[nt][1] = __float_as_uint(Ws[(k0 + 4 + tg) * WS_STRIDE + col]);
            }
#pragma unroll
            for (int mt = 0; mt < 2; mt++)
#pragma unroll
                for (int nt = 0; nt < 8; nt++) {
                    asm volatile(
                        "mma.sync.aligned.m16n8k8.row.col.f32.tf32.tf32.f32 "
                        "{%0,%1,%2,%3}, {%4,%5,%6,%7}, {%8,%9}, {%0,%1,%2,%3};"
                        : "+f"(c2[mt][nt][0]), "+f"(c2[mt][nt][1]),
                          "+f"(c2[mt][nt][2]), "+f"(c2[mt][nt][3])
                        : "r"(a[mt][0]), "r"(a[mt][1]), "r"(a[mt][2]), "r"(a[mt][3]),
                          "r"(b[nt][0]), "r"(b[nt][1]));
                }
        }
        __syncthreads();
    }

    if (!last) {
        // epilogue: bias + ReLU -> Hd
#pragma unroll
        for (int nt = 0; nt < 8; nt++) {
            int col = wn * 64 + nt * 8 + tg * 2;
            float sh0 = b2[col];
            float sh1 = b2[col + 1];
#pragma unroll
            for (int mt = 0; mt < 2; mt++) {
                int r0 = row0 + wm * 32 + mt * 16 + gq;
#pragma unroll
                for (int half = 0; half < 2; half++) {
                    int row = r0 + half * 8;
                    if (row >= NN) continue;
                    float v0 = fmaxf(c2[mt][nt][half * 2 + 0] + sh0, 0.f);
                    float v1 = fmaxf(c2[mt][nt][half * 2 + 1] + sh1, 0.f);
                    *((float2*)&Hd[row * 128 + col]) = make_float2(v0, v1);
                }
            }
        }
    } else {
        // fused pool+classify: rowdot[r] = sum_col ReLU(h)*Wc[col]; out[batch] += rowdot
        float* rowdot = As;  // 128 floats
        if (tid < 128) rowdot[tid] = 0.f;
        __syncthreads();
#pragma unroll
        for (int mt = 0; mt < 2; mt++) {
#pragma unroll
            for (int half = 0; half < 2; half++) {
                int r = wm * 32 + mt * 16 + gq + half * 8;
                if (row0 + r >= NN) continue;
                float p = 0.f;
#pragma unroll
                for (int nt = 0; nt < 8; nt++) {
                    int col = wn * 64 + nt * 8 + tg * 2;
                    float v0 = fmaxf(c2[mt][nt][half * 2 + 0] + b2[col], 0.f);
                    float v1 = fmaxf(c2[mt][nt][half * 2 + 1] + b2[col + 1], 0.f);
                    p += v0 * Wc[col] + v1 * Wc[col + 1];
                }
                atomicAdd(&rowdot[r], p);
            }
        }
        __syncthreads();
        if (tid < 128) {
            int row = row0 + tid;
            if (row < NN) atomicAdd(&out[batch[row]], rowdot[tid]);
        }
    }
}

extern "C" void kernel_launch(void* const* d_in, const int* in_sizes, int n_in,
                              void* d_out, int out_size) {
    const float* x    = (const float*)d_in[0];
    const int* ei     = (const int*)d_in[1];
    const int* batch  = (const int*)d_in[2];
    const float* W1_0 = (const float*)d_in[3];
    const float* b1_0 = (const float*)d_in[4];
    const float* g_0  = (const float*)d_in[5];
    const float* be_0 = (const float*)d_in[6];
    const float* m_0  = (const float*)d_in[7];
    const float* v_0  = (const float*)d_in[8];
    const float* W2_0 = (const float*)d_in[9];
    const float* b2_0 = (const float*)d_in[10];
    const float* W1s  = (const float*)d_in[11];
    const float* b1s  = (const float*)d_in[12];
    const float* gs   = (const float*)d_in[13];
    const float* bes  = (const float*)d_in[14];
    const float* ms   = (const float*)d_in[15];
    const float* vs   = (const float*)d_in[16];
    const float* W2s  = (const float*)d_in[17];
    const float* b2s  = (const float*)d_in[18];
    const float* Wc   = (const float*)d_in[19];
    const float* bc   = (const float*)d_in[20];
    float* out = (float*)d_out;

    cudaFuncSetAttribute(k_fused, cudaFuncAttributeMaxDynamicSharedMemorySize, SMEM_BYTES);

    const int T = 256;
    const int gemm_grid = (NN + 127) / 128;

    // ---- CSR build (dst-sorted adjacency) ----
    k_zero_deg<<<(NN + T - 1) / T, T>>>();
    k_hist<<<(EE + T - 1) / T, T>>>(ei);
    k_scan1<<<NB_SCAN, 1024>>>();
    k_scan2<<<1, 128>>>();
    k_scan3<<<(NN + T - 1) / T, T>>>();
    k_reorder<<<(EE + T - 1) / T, T>>>(ei);

    // ---- layer 0 (in=3): writes hbuf0 ----
    k_gather3<<<(NN + T - 1) / T, T>>>(x);
    k_init_out<<<(GG + T - 1) / T, T>>>(bc, out);
    k_fused<<<gemm_grid, 256, SMEM_BYTES>>>(1, 0, 0, 0, W1_0, b1_0, g_0, be_0, m_0, v_0,
                                            W2_0, b2_0, batch, Wc, out);

    // ---- layers 1..4 (gather fused; ping-pong buffers) ----
    for (int l = 0; l < 4; l++) {
        int last = (l == 3) ? 1 : 0;
        int hsrc = l & 1;         // layer0 wrote buf0; then 0,1,0,1
        int hdst = (l + 1) & 1;
        k_fused<<<gemm_grid, 256, SMEM_BYTES>>>(0, last, hsrc, hdst,
            W1s + l * HH * HH, b1s + l * HH,
            gs + l * HH, bes + l * HH, ms + l * HH, vs + l * HH,
            W2s + l * HH * HH, b2s + l * HH, batch, Wc, out);
    }
}

// round 9
// speedup vs baseline: 1.1519x; 1.1519x over previous
#include <cuda_runtime.h>
#include <cstdint>

#define NN 100000
#define EE 600000
#define HH 128
#define GG 1000
#define BN_EPS 1e-5f
#define NB_SCAN 98   // ceil(NN/1024)

// ---- scratch (alloc-free: __device__ globals) ----
__device__ float g_t[NN * HH];     // h + agg (pre-MLP input)
__device__ float g_h[NN * HH];     // layer output features
__device__ float g_t3[NN * 3];     // layer-0 pre-MLP (3 feats)
// CSR scratch
__device__ int g_deg[NN];
__device__ int g_rowptr[NN + 1];
__device__ int g_cursor[NN];
__device__ int g_bsum[128];
__device__ int g_csr[EE];

// smem layout (floats)
#define US_STRIDE 132
#define AS_STRIDE 36
#define WS_STRIDE 136
#define US_OFF 0
#define AS_OFF (128 * US_STRIDE)
#define WS_OFF (AS_OFF + 128 * AS_STRIDE)
#define SMEM_FLOATS (WS_OFF + 32 * WS_STRIDE)
#define SMEM_BYTES (SMEM_FLOATS * 4)

__device__ __forceinline__ uint32_t f2tf32(float f) {
    uint32_t o;
    asm("cvt.rna.tf32.f32 %0, %1;" : "=r"(o) : "f"(f));
    return o;
}

// ================= CSR build =================
__global__ void k_zero_deg() {
    int i = blockIdx.x * blockDim.x + threadIdx.x;
    if (i < NN) g_deg[i] = 0;
}

__global__ void k_hist(const int* __restrict__ ei) {
    int e = blockIdx.x * blockDim.x + threadIdx.x;
    if (e < EE) atomicAdd(&g_deg[ei[EE + e]], 1);
}

__global__ __launch_bounds__(1024) void k_scan1() {
    __shared__ int s[1024];
    int tid = threadIdx.x;
    int i = blockIdx.x * 1024 + tid;
    int v = (i < NN) ? g_deg[i] : 0;
    s[tid] = v;
    __syncthreads();
#pragma unroll
    for (int off = 1; off < 1024; off <<= 1) {
        int t = (tid >= off) ? s[tid - off] : 0;
        __syncthreads();
        s[tid] += t;
        __syncthreads();
    }
    if (i < NN) g_rowptr[i] = s[tid] - v;
    if (tid == 1023) g_bsum[blockIdx.x] = s[1023];
}

__global__ void k_scan2() {
    __shared__ int s[128];
    int tid = threadIdx.x;
    int v = (tid < NB_SCAN) ? g_bsum[tid] : 0;
    s[tid] = v;
    __syncthreads();
#pragma unroll
    for (int off = 1; off < 128; off <<= 1) {
        int t = (tid >= off) ? s[tid - off] : 0;
        __syncthreads();
        s[tid] += t;
        __syncthreads();
    }
    if (tid < NB_SCAN) g_bsum[tid] = s[tid] - v;
}

__global__ void k_scan3() {
    int i = blockIdx.x * blockDim.x + threadIdx.x;
    if (i < NN) {
        int r = g_rowptr[i] + g_bsum[i >> 10];
        g_rowptr[i] = r;
        g_cursor[i] = r;
    }
    if (i == 0) g_rowptr[NN] = EE;
}

__global__ void k_reorder(const int* __restrict__ ei) {
    int e = blockIdx.x * blockDim.x + threadIdx.x;
    if (e >= EE) return;
    int s = ei[e];
    int d = ei[EE + e];
    int pos = atomicAdd(&g_cursor[d], 1);
    g_csr[pos] = s;
}

// ================= gathers =================
__global__ void k_gather3(const float* __restrict__ x) {
    int n = blockIdx.x * blockDim.x + threadIdx.x;
    if (n >= NN) return;
    int beg = g_rowptr[n], end = g_rowptr[n + 1];
    float a0 = x[n * 3 + 0], a1 = x[n * 3 + 1], a2 = x[n * 3 + 2];
    for (int p = beg; p < end; p++) {
        int s = g_csr[p];
        a0 += x[s * 3 + 0];
        a1 += x[s * 3 + 1];
        a2 += x[s * 3 + 2];
    }
    g_t3[n * 3 + 0] = a0;
    g_t3[n * 3 + 1] = a1;
    g_t3[n * 3 + 2] = a2;
}

// layers 1..4: g_t[n] = g_h[n] + sum_{s in N(n)} g_h[s]; warp per node
__global__ __launch_bounds__(256) void k_gather() {
    int n = blockIdx.x * 8 + (threadIdx.x >> 5);
    if (n >= NN) return;
    int lane = threadIdx.x & 31;
    int beg = g_rowptr[n], end = g_rowptr[n + 1];
    float4 acc = *((const float4*)&g_h[n * HH + lane * 4]);
    int p = beg;
    // 4-deep pipeline to overlap dependent L2 loads
    for (; p + 3 < end; p += 4) {
        int s0 = g_csr[p], s1 = g_csr[p + 1], s2 = g_csr[p + 2], s3 = g_csr[p + 3];
        float4 v0 = *((const float4*)&g_h[s0 * HH + lane * 4]);
        float4 v1 = *((const float4*)&g_h[s1 * HH + lane * 4]);
        float4 v2 = *((const float4*)&g_h[s2 * HH + lane * 4]);
        float4 v3 = *((const float4*)&g_h[s3 * HH + lane * 4]);
        acc.x += (v0.x + v1.x) + (v2.x + v3.x);
        acc.y += (v0.y + v1.y) + (v2.y + v3.y);
        acc.z += (v0.z + v1.z) + (v2.z + v3.z);
        acc.w += (v0.w + v1.w) + (v2.w + v3.w);
    }
    for (; p < end; p++) {
        int s0 = g_csr[p];
        float4 v0 = *((const float4*)&g_h[s0 * HH + lane * 4]);
        acc.x += v0.x;
        acc.y += v0.y;
        acc.z += v0.z;
        acc.w += v0.w;
    }
    *((float4*)&g_t[n * HH + lane * 4]) = acc;
}

// ================= out init =================
__global__ void k_init_out(const float* __restrict__ bc, float* __restrict__ out) {
    int g = blockIdx.x * blockDim.x + threadIdx.x;
    if (g < GG) out[g] = bc[0];
}

// ================= fused per-layer MLP =================
// h = ReLU(ReLU(BN(t@W1+b1)) @ W2 + b2); stage1 result in smem (tf32)
// last layer: epilogue reduces ReLU(h)@Wc into out[batch[row]] (no g_h store)
__global__ __launch_bounds__(256, 2) void k_fused(
    int layer0, int last,
    const float* __restrict__ W1, const float* __restrict__ b1,
    const float* __restrict__ gam, const float* __restrict__ bet,
    const float* __restrict__ mu, const float* __restrict__ var,
    const float* __restrict__ W2, const float* __restrict__ b2,
    const int* __restrict__ batch, const float* __restrict__ Wc,
    float* __restrict__ out) {
    extern __shared__ float smem[];
    float* Us = smem + US_OFF;
    float* As = smem + AS_OFF;
    float* Ws = smem + WS_OFF;

    int tid = threadIdx.x;
    int warp = tid >> 5, lane = tid & 31;
    int wm = warp & 3;
    int wn = warp >> 2;
    int gq = lane >> 2;
    int tg = lane & 3;
    int row0 = blockIdx.x * 128;

    // ---- stage 1 ----
    if (layer0) {
        float* W1s = As;
        float* sc = As + 384;
        float* sh = As + 512;
        for (int i = tid; i < 384; i += 256) W1s[i] = W1[i];
        if (tid < 128) {
            float s = gam[tid] * rsqrtf(var[tid] + BN_EPS);
            sc[tid] = s;
            sh[tid] = bet[tid] + (b1[tid] - mu[tid]) * s;
        }
        __syncthreads();
#pragma unroll 4
        for (int i = 0; i < 64; i++) {
            int idx = tid + i * 256;
            int r = idx >> 7, c = idx & 127;
            int row = row0 + r;
            float x0 = 0.f, x1 = 0.f, x2 = 0.f;
            if (row < NN) {
                x0 = g_t3[row * 3 + 0];
                x1 = g_t3[row * 3 + 1];
                x2 = g_t3[row * 3 + 2];
            }
            float u = x0 * W1s[c] + x1 * W1s[128 + c] + x2 * W1s[256 + c];
            u = fmaxf(u * sc[c] + sh[c], 0.f);
            Us[r * US_STRIDE + c] = __uint_as_float(f2tf32(u));
        }
        __syncthreads();
    } else {
        float c1[2][8][4];
#pragma unroll
        for (int mt = 0; mt < 2; mt++)
#pragma unroll
            for (int nt = 0; nt < 8; nt++)
#pragma unroll
                for (int r = 0; r < 4; r++) c1[mt][nt][r] = 0.f;

        for (int kc = 0; kc < 4; kc++) {
#pragma unroll
            for (int i = 0; i < 4; i++) {
                int r = (tid >> 3) + i * 32;
                int q = tid & 7;
                int row = row0 + r;
                float4 v = make_float4(0.f, 0.f, 0.f, 0.f);
                if (row < NN) v = *((const float4*)&g_t[row * 128 + kc * 32 + q * 4]);
                As[r * AS_STRIDE + q * 4 + 0] = __uint_as_float(f2tf32(v.x));
                As[r * AS_STRIDE + q * 4 + 1] = __uint_as_float(f2tf32(v.y));
                As[r * AS_STRIDE + q * 4 + 2] = __uint_as_float(f2tf32(v.z));
                As[r * AS_STRIDE + q * 4 + 3] = __uint_as_float(f2tf32(v.w));
            }
#pragma unroll
            for (int i = 0; i < 4; i++) {
                int idx = tid + i * 256;
                int k = idx >> 5;
                int q = idx & 31;
                float4 v = *((const float4*)&W1[(kc * 32 + k) * 128 + q * 4]);
                Ws[k * WS_STRIDE + q * 4 + 0] = __uint_as_float(f2tf32(v.x));
                Ws[k * WS_STRIDE + q * 4 + 1] = __uint_as_float(f2tf32(v.y));
                Ws[k * WS_STRIDE + q * 4 + 2] = __uint_as_float(f2tf32(v.z));
                Ws[k * WS_STRIDE + q * 4 + 3] = __uint_as_float(f2tf32(v.w));
            }
            __syncthreads();
#pragma unroll
            for (int ks = 0; ks < 4; ks++) {
                int k0 = ks * 8;
                uint32_t a[2][4];
#pragma unroll
                for (int mt = 0; mt < 2; mt++) {
                    int rb = wm * 32 + mt * 16;
                    a[mt][0] = __float_as_uint(As[(rb + gq) * AS_STRIDE + k0 + tg]);
                    a[mt][1] = __float_as_uint(As[(rb + gq + 8) * AS_STRIDE + k0 + tg]);
                    a[mt][2] = __float_as_uint(As[(rb + gq) * AS_STRIDE + k0 + tg + 4]);
                    a[mt][3] = __float_as_uint(As[(rb + gq + 8) * AS_STRIDE + k0 + tg + 4]);
                }
                uint32_t b[8][2];
#pragma unroll
                for (int nt = 0; nt < 8; nt++) {
                    int col = wn * 64 + nt * 8 + gq;
                    b[nt][0] = __float_as_uint(Ws[(k0 + tg) * WS_STRIDE + col]);
                    b[nt][1] = __float_as_uint(Ws[(k0 + 4 + tg) * WS_STRIDE + col]);
                }
#pragma unroll
                for (int mt = 0; mt < 2; mt++)
#pragma unroll
                    for (int nt = 0; nt < 8; nt++) {
                        asm volatile(
                            "mma.sync.aligned.m16n8k8.row.col.f32.tf32.tf32.f32 "
                            "{%0,%1,%2,%3}, {%4,%5,%6,%7}, {%8,%9}, {%0,%1,%2,%3};"
                            : "+f"(c1[mt][nt][0]), "+f"(c1[mt][nt][1]),
                              "+f"(c1[mt][nt][2]), "+f"(c1[mt][nt][3])
                            : "r"(a[mt][0]), "r"(a[mt][1]), "r"(a[mt][2]), "r"(a[mt][3]),
                              "r"(b[nt][0]), "r"(b[nt][1]));
                    }
            }
            __syncthreads();
        }

        // BN + ReLU -> Us (tf32)
#pragma unroll
        for (int nt = 0; nt < 8; nt++) {
            int col = wn * 64 + nt * 8 + tg * 2;
            float s0 = gam[col] * rsqrtf(var[col] + BN_EPS);
            float s1 = gam[col + 1] * rsqrtf(var[col + 1] + BN_EPS);
            float sh0 = bet[col] + (b1[col] - mu[col]) * s0;
            float sh1 = bet[col + 1] + (b1[col + 1] - mu[col + 1]) * s1;
#pragma unroll
            for (int mt = 0; mt < 2; mt++) {
                int rb = wm * 32 + mt * 16 + gq;
#pragma unroll
                for (int half = 0; half < 2; half++) {
                    int r = rb + half * 8;
                    float v0 = fmaxf(c1[mt][nt][half * 2 + 0] * s0 + sh0, 0.f);
                    float v1 = fmaxf(c1[mt][nt][half * 2 + 1] * s1 + sh1, 0.f);
                    Us[r * US_STRIDE + col] = __uint_as_float(f2tf32(v0));
                    Us[r * US_STRIDE + col + 1] = __uint_as_float(f2tf32(v1));
                }
            }
        }
        __syncthreads();
    }

    // ---- stage 2: h = ReLU(Us @ W2 + b2) ----
    float c2[2][8][4];
#pragma unroll
    for (int mt = 0; mt < 2; mt++)
#pragma unroll
        for (int nt = 0; nt < 8; nt++)
#pragma unroll
            for (int r = 0; r < 4; r++) c2[mt][nt][r] = 0.f;

    for (int kc = 0; kc < 4; kc++) {
#pragma unroll
        for (int i = 0; i < 4; i++) {
            int idx = tid + i * 256;
            int k = idx >> 5;
            int q = idx & 31;
            float4 v = *((const float4*)&W2[(kc * 32 + k) * 128 + q * 4]);
            Ws[k * WS_STRIDE + q * 4 + 0] = __uint_as_float(f2tf32(v.x));
            Ws[k * WS_STRIDE + q * 4 + 1] = __uint_as_float(f2tf32(v.y));
            Ws[k * WS_STRIDE + q * 4 + 2] = __uint_as_float(f2tf32(v.z));
            Ws[k * WS_STRIDE + q * 4 + 3] = __uint_as_float(f2tf32(v.w));
        }
        __syncthreads();
#pragma unroll
        for (int ks = 0; ks < 4; ks++) {
            int k0 = ks * 8;
            int kcol = kc * 32 + k0;
            uint32_t a[2][4];
#pragma unroll
            for (int mt = 0; mt < 2; mt++) {
                int rb = wm * 32 + mt * 16;
                a[mt][0] = __float_as_uint(Us[(rb + gq) * US_STRIDE + kcol + tg]);
                a[mt][1] = __float_as_uint(Us[(rb + gq + 8) * US_STRIDE + kcol + tg]);
                a[mt][2] = __float_as_uint(Us[(rb + gq) * US_STRIDE + kcol + tg + 4]);
                a[mt][3] = __float_as_uint(Us[(rb + gq + 8) * US_STRIDE + kcol + tg + 4]);
            }
            uint32_t b[8][2];
#pragma unroll
            for (int nt = 0; nt < 8; nt++) {
                int col = wn * 64 + nt * 8 + gq;
                b[nt][0] = __float_as_uint(Ws[(k0 + tg) * WS_STRIDE + col]);
                b[nt][1] = __float_as_uint(Ws[(k0 + 4 + tg) * WS_STRIDE + col]);
            }
#pragma unroll
            for (int mt = 0; mt < 2; mt++)
#pragma unroll
                for (int nt = 0; nt < 8; nt++) {
                    asm volatile(
                        "mma.sync.aligned.m16n8k8.row.col.f32.tf32.tf32.f32 "
                        "{%0,%1,%2,%3}, {%4,%5,%6,%7}, {%8,%9}, {%0,%1,%2,%3};"
                        : "+f"(c2[mt][nt][0]), "+f"(c2[mt][nt][1]),
                          "+f"(c2[mt][nt][2]), "+f"(c2[mt][nt][3])
                        : "r"(a[mt][0]), "r"(a[mt][1]), "r"(a[mt][2]), "r"(a[mt][3]),
                          "r"(b[nt][0]), "r"(b[nt][1]));
                }
        }
        __syncthreads();
    }

    if (!last) {
        // epilogue: bias + ReLU -> g_h
#pragma unroll
        for (int nt = 0; nt < 8; nt++) {
            int col = wn * 64 + nt * 8 + tg * 2;
            float sh0 = b2[col];
            float sh1 = b2[col + 1];
#pragma unroll
            for (int mt = 0; mt < 2; mt++) {
                int r0 = row0 + wm * 32 + mt * 16 + gq;
#pragma unroll
                for (int half = 0; half < 2; half++) {
                    int row = r0 + half * 8;
                    if (row >= NN) continue;
                    float v0 = fmaxf(c2[mt][nt][half * 2 + 0] + sh0, 0.f);
                    float v1 = fmaxf(c2[mt][nt][half * 2 + 1] + sh1, 0.f);
                    *((float2*)&g_h[row * 128 + col]) = make_float2(v0, v1);
                }
            }
        }
    } else {
        // fused pool+classify: rowdot[r] = sum_col ReLU(h)*Wc[col]; out[batch] += rowdot
        float* rowdot = As;  // 128 floats
        if (tid < 128) rowdot[tid] = 0.f;
        __syncthreads();
#pragma unroll
        for (int mt = 0; mt < 2; mt++) {
#pragma unroll
            for (int half = 0; half < 2; half++) {
                int r = wm * 32 + mt * 16 + gq + half * 8;
                if (row0 + r >= NN) continue;
                float p = 0.f;
#pragma unroll
                for (int nt = 0; nt < 8; nt++) {
                    int col = wn * 64 + nt * 8 + tg * 2;
                    float v0 = fmaxf(c2[mt][nt][half * 2 + 0] + b2[col], 0.f);
                    float v1 = fmaxf(c2[mt][nt][half * 2 + 1] + b2[col + 1], 0.f);
                    p += v0 * Wc[col] + v1 * Wc[col + 1];
                }
                atomicAdd(&rowdot[r], p);
            }
        }
        __syncthreads();
        if (tid < 128) {
            int row = row0 + tid;
            if (row < NN) atomicAdd(&out[batch[row]], rowdot[tid]);
        }
    }
}

extern "C" void kernel_launch(void* const* d_in, const int* in_sizes, int n_in,
                              void* d_out, int out_size) {
    const float* x    = (const float*)d_in[0];
    const int* ei     = (const int*)d_in[1];
    const int* batch  = (const int*)d_in[2];
    const float* W1_0 = (const float*)d_in[3];
    const float* b1_0 = (const float*)d_in[4];
    const float* g_0  = (const float*)d_in[5];
    const float* be_0 = (const float*)d_in[6];
    const float* m_0  = (const float*)d_in[7];
    const float* v_0  = (const float*)d_in[8];
    const float* W2_0 = (const float*)d_in[9];
    const float* b2_0 = (const float*)d_in[10];
    const float* W1s  = (const float*)d_in[11];
    const float* b1s  = (const float*)d_in[12];
    const float* gs   = (const float*)d_in[13];
    const float* bes  = (const float*)d_in[14];
    const float* ms   = (const float*)d_in[15];
    const float* vs   = (const float*)d_in[16];
    const float* W2s  = (const float*)d_in[17];
    const float* b2s  = (const float*)d_in[18];
    const float* Wc   = (const float*)d_in[19];
    const float* bc   = (const float*)d_in[20];
    float* out = (float*)d_out;

    cudaFuncSetAttribute(k_fused, cudaFuncAttributeMaxDynamicSharedMemorySize, SMEM_BYTES);

    const int T = 256;
    const int gemm_grid = (NN + 127) / 128;

    // ---- CSR build (dst-sorted adjacency) ----
    k_zero_deg<<<(NN + T - 1) / T, T>>>();
    k_hist<<<(EE + T - 1) / T, T>>>(ei);
    k_scan1<<<NB_SCAN, 1024>>>();
    k_scan2<<<1, 128>>>();
    k_scan3<<<(NN + T - 1) / T, T>>>();
    k_reorder<<<(EE + T - 1) / T, T>>>(ei);

    // ---- layer 0 (in=3) ----
    k_gather3<<<(NN + T - 1) / T, T>>>(x);
    k_init_out<<<(GG + T - 1) / T, T>>>(bc, out);
    k_fused<<<gemm_grid, 256, SMEM_BYTES>>>(1, 0, W1_0, b1_0, g_0, be_0, m_0, v_0,
                                            W2_0, b2_0, batch, Wc, out);

    // ---- layers 1..4 (separate high-occupancy gather) ----
    for (int l = 0; l < 4; l++) {
        int last = (l == 3) ? 1 : 0;
        k_gather<<<(NN + 7) / 8, 256>>>();
        k_fused<<<gemm_grid, 256, SMEM_BYTES>>>(0, last,
            W1s + l * HH * HH, b1s + l * HH,
            gs + l * HH, bes + l * HH, ms + l * HH, vs + l * HH,
            W2s + l * HH * HH, b2s + l * HH, batch, Wc, out);
    }
}

// round 10
// speedup vs baseline: 1.3437x; 1.1665x over previous
#include <cuda_runtime.h>
#include <cuda_fp16.h>
#include <cstdint>

#define NN 100000
#define EE 600000
#define HH 128
#define GG 1000
#define BN_EPS 1e-5f
#define NB_SCAN 98   // ceil(NN/1024)

// ---- scratch (alloc-free: __device__ globals) ----
__device__ __half g_t[NN * HH];    // h + agg (pre-MLP input), fp16
__device__ __half g_h[NN * HH];    // layer output features, fp16
__device__ float g_t3[NN * 3];     // layer-0 pre-MLP (3 feats)
// CSR scratch
__device__ int g_deg[NN];
__device__ int g_rowptr[NN + 1];
__device__ int g_cursor[NN];
__device__ int g_bsum[128];
__device__ int g_csr[EE];

// smem layout (floats)
#define US_STRIDE 132
#define AS_STRIDE 36
#define WS_STRIDE 136
#define US_OFF 0
#define AS_OFF (128 * US_STRIDE)
#define WS_OFF (AS_OFF + 128 * AS_STRIDE)
#define SMEM_FLOATS (WS_OFF + 32 * WS_STRIDE)
#define SMEM_BYTES (SMEM_FLOATS * 4)

__device__ __forceinline__ uint32_t f2tf32(float f) {
    uint32_t o;
    asm("cvt.rna.tf32.f32 %0, %1;" : "=r"(o) : "f"(f));
    return o;
}

// ================= CSR build =================
__global__ void k_zero_deg() {
    int i = blockIdx.x * blockDim.x + threadIdx.x;
    if (i < NN) g_deg[i] = 0;
}

__global__ void k_hist(const int* __restrict__ ei) {
    int e = blockIdx.x * blockDim.x + threadIdx.x;
    if (e < EE) atomicAdd(&g_deg[ei[EE + e]], 1);
}

__global__ __launch_bounds__(1024) void k_scan1() {
    __shared__ int s[1024];
    int tid = threadIdx.x;
    int i = blockIdx.x * 1024 + tid;
    int v = (i < NN) ? g_deg[i] : 0;
    s[tid] = v;
    __syncthreads();
#pragma unroll
    for (int off = 1; off < 1024; off <<= 1) {
        int t = (tid >= off) ? s[tid - off] : 0;
        __syncthreads();
        s[tid] += t;
        __syncthreads();
    }
    if (i < NN) g_rowptr[i] = s[tid] - v;
    if (tid == 1023) g_bsum[blockIdx.x] = s[1023];
}

__global__ void k_scan2() {
    __shared__ int s[128];
    int tid = threadIdx.x;
    int v = (tid < NB_SCAN) ? g_bsum[tid] : 0;
    s[tid] = v;
    __syncthreads();
#pragma unroll
    for (int off = 1; off < 128; off <<= 1) {
        int t = (tid >= off) ? s[tid - off] : 0;
        __syncthreads();
        s[tid] += t;
        __syncthreads();
    }
    if (tid < NB_SCAN) g_bsum[tid] = s[tid] - v;
}

__global__ void k_scan3() {
    int i = blockIdx.x * blockDim.x + threadIdx.x;
    if (i < NN) {
        int r = g_rowptr[i] + g_bsum[i >> 10];
        g_rowptr[i] = r;
        g_cursor[i] = r;
    }
    if (i == 0) g_rowptr[NN] = EE;
}

__global__ void k_reorder(const int* __restrict__ ei) {
    int e = blockIdx.x * blockDim.x + threadIdx.x;
    if (e >= EE) return;
    int s = ei[e];
    int d = ei[EE + e];
    int pos = atomicAdd(&g_cursor[d], 1);
    g_csr[pos] = s;
}

// ================= gathers =================
__global__ void k_gather3(const float* __restrict__ x) {
    int n = blockIdx.x * blockDim.x + threadIdx.x;
    if (n >= NN) return;
    int beg = g_rowptr[n], end = g_rowptr[n + 1];
    float a0 = x[n * 3 + 0], a1 = x[n * 3 + 1], a2 = x[n * 3 + 2];
    for (int p = beg; p < end; p++) {
        int s = g_csr[p];
        a0 += x[s * 3 + 0];
        a1 += x[s * 3 + 1];
        a2 += x[s * 3 + 2];
    }
    g_t3[n * 3 + 0] = a0;
    g_t3[n * 3 + 1] = a1;
    g_t3[n * 3 + 2] = a2;
}

__device__ __forceinline__ void acc_half4(float4& acc, uint2 r) {
    float2 f0 = __half22float2(*(__half2*)&r.x);
    float2 f1 = __half22float2(*(__half2*)&r.y);
    acc.x += f0.x;
    acc.y += f0.y;
    acc.z += f1.x;
    acc.w += f1.y;
}

// layers 1..4: g_t[n] = g_h[n] + sum_{s in N(n)} g_h[s]; warp per node, fp16 I/O
__global__ __launch_bounds__(256) void k_gather() {
    int n = blockIdx.x * 8 + (threadIdx.x >> 5);
    if (n >= NN) return;
    int lane = threadIdx.x & 31;
    int beg = g_rowptr[n], end = g_rowptr[n + 1];
    float4 acc = make_float4(0.f, 0.f, 0.f, 0.f);
    acc_half4(acc, *((const uint2*)&g_h[n * HH + lane * 4]));
    int p = beg;
    for (; p + 3 < end; p += 4) {
        int s0 = g_csr[p], s1 = g_csr[p + 1], s2 = g_csr[p + 2], s3 = g_csr[p + 3];
        uint2 v0 = *((const uint2*)&g_h[s0 * HH + lane * 4]);
        uint2 v1 = *((const uint2*)&g_h[s1 * HH + lane * 4]);
        uint2 v2 = *((const uint2*)&g_h[s2 * HH + lane * 4]);
        uint2 v3 = *((const uint2*)&g_h[s3 * HH + lane * 4]);
        acc_half4(acc, v0);
        acc_half4(acc, v1);
        acc_half4(acc, v2);
        acc_half4(acc, v3);
    }
    for (; p < end; p++) {
        acc_half4(acc, *((const uint2*)&g_h[g_csr[p] * HH + lane * 4]));
    }
    __half2 o0 = __floats2half2_rn(acc.x, acc.y);
    __half2 o1 = __floats2half2_rn(acc.z, acc.w);
    uint2 o;
    o.x = *(uint32_t*)&o0;
    o.y = *(uint32_t*)&o1;
    *((uint2*)&g_t[n * HH + lane * 4]) = o;
}

// ================= out init =================
__global__ void k_init_out(const float* __restrict__ bc, float* __restrict__ out) {
    int g = blockIdx.x * blockDim.x + threadIdx.x;
    if (g < GG) out[g] = bc[0];
}

// ================= fused per-layer MLP =================
// h = ReLU(ReLU(BN(t@W1+b1)) @ W2 + b2); stage1 result in smem (tf32)
// features in fp16 (mantissa == tf32 mantissa -> no extra precision loss)
// last layer: epilogue reduces ReLU(h)@Wc into out[batch[row]] (no g_h store)
__global__ __launch_bounds__(256, 2) void k_fused(
    int layer0, int last,
    const float* __restrict__ W1, const float* __restrict__ b1,
    const float* __restrict__ gam, const float* __restrict__ bet,
    const float* __restrict__ mu, const float* __restrict__ var,
    const float* __restrict__ W2, const float* __restrict__ b2,
    const int* __restrict__ batch, const float* __restrict__ Wc,
    float* __restrict__ out) {
    extern __shared__ float smem[];
    float* Us = smem + US_OFF;
    float* As = smem + AS_OFF;
    float* Ws = smem + WS_OFF;

    int tid = threadIdx.x;
    int warp = tid >> 5, lane = tid & 31;
    int wm = warp & 3;
    int wn = warp >> 2;
    int gq = lane >> 2;
    int tg = lane & 3;
    int row0 = blockIdx.x * 128;

    // ---- stage 1 ----
    if (layer0) {
        float* W1s = As;
        float* sc = As + 384;
        float* sh = As + 512;
        for (int i = tid; i < 384; i += 256) W1s[i] = W1[i];
        if (tid < 128) {
            float s = gam[tid] * rsqrtf(var[tid] + BN_EPS);
            sc[tid] = s;
            sh[tid] = bet[tid] + (b1[tid] - mu[tid]) * s;
        }
        __syncthreads();
#pragma unroll 4
        for (int i = 0; i < 64; i++) {
            int idx = tid + i * 256;
            int r = idx >> 7, c = idx & 127;
            int row = row0 + r;
            float x0 = 0.f, x1 = 0.f, x2 = 0.f;
            if (row < NN) {
                x0 = g_t3[row * 3 + 0];
                x1 = g_t3[row * 3 + 1];
                x2 = g_t3[row * 3 + 2];
            }
            float u = x0 * W1s[c] + x1 * W1s[128 + c] + x2 * W1s[256 + c];
            u = fmaxf(u * sc[c] + sh[c], 0.f);
            Us[r * US_STRIDE + c] = __uint_as_float(f2tf32(u));
        }
        __syncthreads();
    } else {
        float c1[2][8][4];
#pragma unroll
        for (int mt = 0; mt < 2; mt++)
#pragma unroll
            for (int nt = 0; nt < 8; nt++)
#pragma unroll
                for (int r = 0; r < 4; r++) c1[mt][nt][r] = 0.f;

        for (int kc = 0; kc < 4; kc++) {
            // A chunk from g_t (fp16 -> fp32; already tf32-exact)
#pragma unroll
            for (int i = 0; i < 4; i++) {
                int r = (tid >> 3) + i * 32;
                int q = tid & 7;
                int row = row0 + r;
                uint2 v = make_uint2(0u, 0u);
                if (row < NN) v = *((const uint2*)&g_t[row * 128 + kc * 32 + q * 4]);
                float2 f0 = __half22float2(*(__half2*)&v.x);
                float2 f1 = __half22float2(*(__half2*)&v.y);
                As[r * AS_STRIDE + q * 4 + 0] = f0.x;
                As[r * AS_STRIDE + q * 4 + 1] = f0.y;
                As[r * AS_STRIDE + q * 4 + 2] = f1.x;
                As[r * AS_STRIDE + q * 4 + 3] = f1.y;
            }
#pragma unroll
            for (int i = 0; i < 4; i++) {
                int idx = tid + i * 256;
                int k = idx >> 5;
                int q = idx & 31;
                float4 v = *((const float4*)&W1[(kc * 32 + k) * 128 + q * 4]);
                Ws[k * WS_STRIDE + q * 4 + 0] = __uint_as_float(f2tf32(v.x));
                Ws[k * WS_STRIDE + q * 4 + 1] = __uint_as_float(f2tf32(v.y));
                Ws[k * WS_STRIDE + q * 4 + 2] = __uint_as_float(f2tf32(v.z));
                Ws[k * WS_STRIDE + q * 4 + 3] = __uint_as_float(f2tf32(v.w));
            }
            __syncthreads();
#pragma unroll
            for (int ks = 0; ks < 4; ks++) {
                int k0 = ks * 8;
                uint32_t a[2][4];
#pragma unroll
                for (int mt = 0; mt < 2; mt++) {
                    int rb = wm * 32 + mt * 16;
                    a[mt][0] = __float_as_uint(As[(rb + gq) * AS_STRIDE + k0 + tg]);
                    a[mt][1] = __float_as_uint(As[(rb + gq + 8) * AS_STRIDE + k0 + tg]);
                    a[mt][2] = __float_as_uint(As[(rb + gq) * AS_STRIDE + k0 + tg + 4]);
                    a[mt][3] = __float_as_uint(As[(rb + gq + 8) * AS_STRIDE + k0 + tg + 4]);
                }
                uint32_t b[8][2];
#pragma unroll
                for (int nt = 0; nt < 8; nt++) {
                    int col = wn * 64 + nt * 8 + gq;
                    b[nt][0] = __float_as_uint(Ws[(k0 + tg) * WS_STRIDE + col]);
                    b[nt][1] = __float_as_uint(Ws[(k0 + 4 + tg) * WS_STRIDE + col]);
                }
#pragma unroll
                for (int mt = 0; mt < 2; mt++)
#pragma unroll
                    for (int nt = 0; nt < 8; nt++) {
                        asm volatile(
                            "mma.sync.aligned.m16n8k8.row.col.f32.tf32.tf32.f32 "
                            "{%0,%1,%2,%3}, {%4,%5,%6,%7}, {%8,%9}, {%0,%1,%2,%3};"
                            : "+f"(c1[mt][nt][0]), "+f"(c1[mt][nt][1]),
                              "+f"(c1[mt][nt][2]), "+f"(c1[mt][nt][3])
                            : "r"(a[mt][0]), "r"(a[mt][1]), "r"(a[mt][2]), "r"(a[mt][3]),
                              "r"(b[nt][0]), "r"(b[nt][1]));
                    }
            }
            __syncthreads();
        }

        // BN + ReLU -> Us (tf32)
#pragma unroll
        for (int nt = 0; nt < 8; nt++) {
            int col = wn * 64 + nt * 8 + tg * 2;
            float s0 = gam[col] * rsqrtf(var[col] + BN_EPS);
            float s1 = gam[col + 1] * rsqrtf(var[col + 1] + BN_EPS);
            float sh0 = bet[col] + (b1[col] - mu[col]) * s0;
            float sh1 = bet[col + 1] + (b1[col + 1] - mu[col + 1]) * s1;
#pragma unroll
            for (int mt = 0; mt < 2; mt++) {
                int rb = wm * 32 + mt * 16 + gq;
#pragma unroll
                for (int half = 0; half < 2; half++) {
                    int r = rb + half * 8;
                    float v0 = fmaxf(c1[mt][nt][half * 2 + 0] * s0 + sh0, 0.f);
                    float v1 = fmaxf(c1[mt][nt][half * 2 + 1] * s1 + sh1, 0.f);
                    Us[r * US_STRIDE + col] = __uint_as_float(f2tf32(v0));
                    Us[r * US_STRIDE + col + 1] = __uint_as_float(f2tf32(v1));
                }
            }
        }
        __syncthreads();
    }

    // ---- stage 2: h = ReLU(Us @ W2 + b2) ----
    float c2[2][8][4];
#pragma unroll
    for (int mt = 0; mt < 2; mt++)
#pragma unroll
        for (int nt = 0; nt < 8; nt++)
#pragma unroll
            for (int r = 0; r < 4; r++) c2[mt][nt][r] = 0.f;

    for (int kc = 0; kc < 4; kc++) {
#pragma unroll
        for (int i = 0; i < 4; i++) {
            int idx = tid + i * 256;
            int k = idx >> 5;
            int q = idx & 31;
            float4 v = *((const float4*)&W2[(kc * 32 + k) * 128 + q * 4]);
            Ws[k * WS_STRIDE + q * 4 + 0] = __uint_as_float(f2tf32(v.x));
            Ws[k * WS_STRIDE + q * 4 + 1] = __uint_as_float(f2tf32(v.y));
            Ws[k * WS_STRIDE + q * 4 + 2] = __uint_as_float(f2tf32(v.z));
            Ws[k * WS_STRIDE + q * 4 + 3] = __uint_as_float(f2tf32(v.w));
        }
        __syncthreads();
#pragma unroll
        for (int ks = 0; ks < 4; ks++) {
            int k0 = ks * 8;
            int kcol = kc * 32 + k0;
            uint32_t a[2][4];
#pragma unroll
            for (int mt = 0; mt < 2; mt++) {
                int rb = wm * 32 + mt * 16;
                a[mt][0] = __float_as_uint(Us[(rb + gq) * US_STRIDE + kcol + tg]);
                a[mt][1] = __float_as_uint(Us[(rb + gq + 8) * US_STRIDE + kcol + tg]);
                a[mt][2] = __float_as_uint(Us[(rb + gq) * US_STRIDE + kcol + tg + 4]);
                a[mt][3] = __float_as_uint(Us[(rb + gq + 8) * US_STRIDE + kcol + tg + 4]);
            }
            uint32_t b[8][2];
#pragma unroll
            for (int nt = 0; nt < 8; nt++) {
                int col = wn * 64 + nt * 8 + gq;
                b[nt][0] = __float_as_uint(Ws[(k0 + tg) * WS_STRIDE + col]);
                b[nt][1] = __float_as_uint(Ws[(k0 + 4 + tg) * WS_STRIDE + col]);
            }
#pragma unroll
            for (int mt = 0; mt < 2; mt++)
#pragma unroll
                for (int nt = 0; nt < 8; nt++) {
                    asm volatile(
                        "mma.sync.aligned.m16n8k8.row.col.f32.tf32.tf32.f32 "
                        "{%0,%1,%2,%3}, {%4,%5,%6,%7}, {%8,%9}, {%0,%1,%2,%3};"
                        : "+f"(c2[mt][nt][0]), "+f"(c2[mt][nt][1]),
                          "+f"(c2[mt][nt][2]), "+f"(c2[mt][nt][3])
                        : "r"(a[mt][0]), "r"(a[mt][1]), "r"(a[mt][2]), "r"(a[mt][3]),
                          "r"(b[nt][0]), "r"(b[nt][1]));
                }
        }
        __syncthreads();
    }

    if (!last) {
        // epilogue: bias + ReLU -> g_h (fp16)
#pragma unroll
        for (int nt = 0; nt < 8; nt++) {
            int col = wn * 64 + nt * 8 + tg * 2;
            float sh0 = b2[col];
            float sh1 = b2[col + 1];
#pragma unroll
            for (int mt = 0; mt < 2; mt++) {
                int r0 = row0 + wm * 32 + mt * 16 + gq;
#pragma unroll
                for (int half = 0; half < 2; half++) {
                    int row = r0 + half * 8;
                    if (row >= NN) continue;
                    float v0 = fmaxf(c2[mt][nt][half * 2 + 0] + sh0, 0.f);
                    float v1 = fmaxf(c2[mt][nt][half * 2 + 1] + sh1, 0.f);
                    *((__half2*)&g_h[row * 128 + col]) = __floats2half2_rn(v0, v1);
                }
            }
        }
    } else {
        // fused pool+classify
        float* rowdot = As;  // 128 floats
        if (tid < 128) rowdot[tid] = 0.f;
        __syncthreads();
#pragma unroll
        for (int mt = 0; mt < 2; mt++) {
#pragma unroll
            for (int half = 0; half < 2; half++) {
                int r = wm * 32 + mt * 16 + gq + half * 8;
                if (row0 + r >= NN) continue;
                float p = 0.f;
#pragma unroll
                for (int nt = 0; nt < 8; nt++) {
                    int col = wn * 64 + nt * 8 + tg * 2;
                    float v0 = fmaxf(c2[mt][nt][half * 2 + 0] + b2[col], 0.f);
                    float v1 = fmaxf(c2[mt][nt][half * 2 + 1] + b2[col + 1], 0.f);
                    p += v0 * Wc[col] + v1 * Wc[col + 1];
                }
                atomicAdd(&rowdot[r], p);
            }
        }
        __syncthreads();
        if (tid < 128) {
            int row = row0 + tid;
            if (row < NN) atomicAdd(&out[batch[row]], rowdot[tid]);
        }
    }
}

extern "C" void kernel_launch(void* const* d_in, const int* in_sizes, int n_in,
                              void* d_out, int out_size) {
    const float* x    = (const float*)d_in[0];
    const int* ei     = (const int*)d_in[1];
    const int* batch  = (const int*)d_in[2];
    const float* W1_0 = (const float*)d_in[3];
    const float* b1_0 = (const float*)d_in[4];
    const float* g_0  = (const float*)d_in[5];
    const float* be_0 = (const float*)d_in[6];
    const float* m_0  = (const float*)d_in[7];
    const float* v_0  = (const float*)d_in[8];
    const float* W2_0 = (const float*)d_in[9];
    const float* b2_0 = (const float*)d_in[10];
    const float* W1s  = (const float*)d_in[11];
    const float* b1s  = (const float*)d_in[12];
    const float* gs   = (const float*)d_in[13];
    const float* bes  = (const float*)d_in[14];
    const float* ms   = (const float*)d_in[15];
    const float* vs   = (const float*)d_in[16];
    const float* W2s  = (const float*)d_in[17];
    const float* b2s  = (const float*)d_in[18];
    const float* Wc   = (const float*)d_in[19];
    const float* bc   = (const float*)d_in[20];
    float* out = (float*)d_out;

    cudaFuncSetAttribute(k_fused, cudaFuncAttributeMaxDynamicSharedMemorySize, SMEM_BYTES);

    const int T = 256;
    const int gemm_grid = (NN + 127) / 128;

    // ---- CSR build (dst-sorted adjacency) ----
    k_zero_deg<<<(NN + T - 1) / T, T>>>();
    k_hist<<<(EE + T - 1) / T, T>>>(ei);
    k_scan1<<<NB_SCAN, 1024>>>();
    k_scan2<<<1, 128>>>();
    k_scan3<<<(NN + T - 1) / T, T>>>();
    k_reorder<<<(EE + T - 1) / T, T>>>(ei);

    // ---- layer 0 (in=3) ----
    k_gather3<<<(NN + T - 1) / T, T>>>(x);
    k_init_out<<<(GG + T - 1) / T, T>>>(bc, out);
    k_fused<<<gemm_grid, 256, SMEM_BYTES>>>(1, 0, W1_0, b1_0, g_0, be_0, m_0, v_0,
                                            W2_0, b2_0, batch, Wc, out);

    // ---- layers 1..4 ----
    for (int l = 0; l < 4; l++) {
        int last = (l == 3) ? 1 : 0;
        k_gather<<<(NN + 7) / 8, 256>>>();
        k_fused<<<gemm_grid, 256, SMEM_BYTES>>>(0, last,
            W1s + l * HH * HH, b1s + l * HH,
            gs + l * HH, bes + l * HH, ms + l * HH, vs + l * HH,
            W2s + l * HH * HH, b2s + l * HH, batch, Wc, out);
    }
}

// round 11
// speedup vs baseline: 1.7389x; 1.2941x over previous
#include <cuda_runtime.h>
#include <cuda_fp16.h>
#include <cstdint>

#define NN 100000
#define EE 600000
#define HH 128
#define GG 1000
#define BN_EPS 1e-5f
#define NB_SCAN 98   // ceil(NN/1024)

// ---- scratch (alloc-free: __device__ globals) ----
__device__ __half g_t[NN * HH];    // h + agg (pre-MLP input), fp16
__device__ __half g_h[NN * HH];    // layer output features, fp16
__device__ float g_t3[NN * 3];     // layer-0 pre-MLP (3 feats)
// CSR scratch
__device__ int g_deg[NN];
__device__ int g_rowptr[NN + 1];
__device__ int g_cursor[NN];
__device__ int g_bsum[128];
__device__ int g_csr[EE];

// smem layout: Us (fp16 A / activations) + Wp (packed fp16 weights, k-pairs)
#define US_HSTRIDE 136                    // halves; word bank = 4r+tg (conflict-free)
#define US_BYTES (128 * US_HSTRIDE * 2)   // 34816
#define WP_WSTRIDE 132                    // words;  bank = 4tg+gq (conflict-free)
#define WP_BYTES (64 * WP_WSTRIDE * 4)    // 33792
#define SMEM_BYTES (US_BYTES + WP_BYTES)  // 68608

// ================= CSR build =================
__global__ void k_zero_deg() {
    int i = blockIdx.x * blockDim.x + threadIdx.x;
    if (i < NN) g_deg[i] = 0;
}

__global__ void k_hist(const int* __restrict__ ei) {
    int e = blockIdx.x * blockDim.x + threadIdx.x;
    if (e < EE) atomicAdd(&g_deg[ei[EE + e]], 1);
}

__global__ __launch_bounds__(1024) void k_scan1() {
    __shared__ int s[1024];
    int tid = threadIdx.x;
    int i = blockIdx.x * 1024 + tid;
    int v = (i < NN) ? g_deg[i] : 0;
    s[tid] = v;
    __syncthreads();
#pragma unroll
    for (int off = 1; off < 1024; off <<= 1) {
        int t = (tid >= off) ? s[tid - off] : 0;
        __syncthreads();
        s[tid] += t;
        __syncthreads();
    }
    if (i < NN) g_rowptr[i] = s[tid] - v;
    if (tid == 1023) g_bsum[blockIdx.x] = s[1023];
}

__global__ void k_scan2() {
    __shared__ int s[128];
    int tid = threadIdx.x;
    int v = (tid < NB_SCAN) ? g_bsum[tid] : 0;
    s[tid] = v;
    __syncthreads();
#pragma unroll
    for (int off = 1; off < 128; off <<= 1) {
        int t = (tid >= off) ? s[tid - off] : 0;
        __syncthreads();
        s[tid] += t;
        __syncthreads();
    }
    if (tid < NB_SCAN) g_bsum[tid] = s[tid] - v;
}

__global__ void k_scan3() {
    int i = blockIdx.x * blockDim.x + threadIdx.x;
    if (i < NN) {
        int r = g_rowptr[i] + g_bsum[i >> 10];
        g_rowptr[i] = r;
        g_cursor[i] = r;
    }
    if (i == 0) g_rowptr[NN] = EE;
}

__global__ void k_reorder(const int* __restrict__ ei) {
    int e = blockIdx.x * blockDim.x + threadIdx.x;
    if (e >= EE) return;
    int s = ei[e];
    int d = ei[EE + e];
    int pos = atomicAdd(&g_cursor[d], 1);
    g_csr[pos] = s;
}

// ================= gathers =================
__global__ void k_gather3(const float* __restrict__ x) {
    int n = blockIdx.x * blockDim.x + threadIdx.x;
    if (n >= NN) return;
    int beg = g_rowptr[n], end = g_rowptr[n + 1];
    float a0 = x[n * 3 + 0], a1 = x[n * 3 + 1], a2 = x[n * 3 + 2];
    for (int p = beg; p < end; p++) {
        int s = g_csr[p];
        a0 += x[s * 3 + 0];
        a1 += x[s * 3 + 1];
        a2 += x[s * 3 + 2];
    }
    g_t3[n * 3 + 0] = a0;
    g_t3[n * 3 + 1] = a1;
    g_t3[n * 3 + 2] = a2;
}

__device__ __forceinline__ void acc_half4(float4& acc, uint2 r) {
    float2 f0 = __half22float2(*(__half2*)&r.x);
    float2 f1 = __half22float2(*(__half2*)&r.y);
    acc.x += f0.x;
    acc.y += f0.y;
    acc.z += f1.x;
    acc.w += f1.y;
}

__global__ __launch_bounds__(256) void k_gather() {
    int n = blockIdx.x * 8 + (threadIdx.x >> 5);
    if (n >= NN) return;
    int lane = threadIdx.x & 31;
    int beg = g_rowptr[n], end = g_rowptr[n + 1];
    float4 acc = make_float4(0.f, 0.f, 0.f, 0.f);
    acc_half4(acc, *((const uint2*)&g_h[n * HH + lane * 4]));
    int p = beg;
    for (; p + 3 < end; p += 4) {
        int s0 = g_csr[p], s1 = g_csr[p + 1], s2 = g_csr[p + 2], s3 = g_csr[p + 3];
        uint2 v0 = *((const uint2*)&g_h[s0 * HH + lane * 4]);
        uint2 v1 = *((const uint2*)&g_h[s1 * HH + lane * 4]);
        uint2 v2 = *((const uint2*)&g_h[s2 * HH + lane * 4]);
        uint2 v3 = *((const uint2*)&g_h[s3 * HH + lane * 4]);
        acc_half4(acc, v0);
        acc_half4(acc, v1);
        acc_half4(acc, v2);
        acc_half4(acc, v3);
    }
    for (; p < end; p++) {
        acc_half4(acc, *((const uint2*)&g_h[g_csr[p] * HH + lane * 4]));
    }
    __half2 o0 = __floats2half2_rn(acc.x, acc.y);
    __half2 o1 = __floats2half2_rn(acc.z, acc.w);
    uint2 o;
    o.x = *(uint32_t*)&o0;
    o.y = *(uint32_t*)&o1;
    *((uint2*)&g_t[n * HH + lane * 4]) = o;
}

// ================= out init =================
__global__ void k_init_out(const float* __restrict__ bc, float* __restrict__ out) {
    int g = blockIdx.x * blockDim.x + threadIdx.x;
    if (g < GG) out[g] = bc[0];
}

// ================= helpers for k_fused =================
// pack W (fp32 row-major [128,128]) into Wp as k-pair half2: Wp[kp][col]=(W[2kp][col],W[2kp+1][col])
__device__ __forceinline__ void pack_weights(uint32_t* Wp, const float* __restrict__ W, int tid) {
#pragma unroll
    for (int i = 0; i < 8; i++) {
        int idx = tid + i * 256;      // 0..2047
        int kp = idx >> 5;            // 0..63
        int col = (idx & 31) * 4;     // 0..124
        float4 v0 = *((const float4*)&W[(2 * kp) * 128 + col]);
        float4 v1 = *((const float4*)&W[(2 * kp + 1) * 128 + col]);
        uint32_t* dst = &Wp[kp * WP_WSTRIDE + col];
        __half2 h;
        h = __floats2half2_rn(v0.x, v1.x); dst[0] = *(uint32_t*)&h;
        h = __floats2half2_rn(v0.y, v1.y); dst[1] = *(uint32_t*)&h;
        h = __floats2half2_rn(v0.z, v1.z); dst[2] = *(uint32_t*)&h;
        h = __floats2half2_rn(v0.w, v1.w); dst[3] = *(uint32_t*)&h;
    }
}

// full-K (128) fp16 MMA: acc += Us(rows) @ Wp
__device__ __forceinline__ void mma_fullk(
    float c[2][8][4], const __half* Us, const uint32_t* Wp,
    int wm, int wn, int gq, int tg) {
#pragma unroll
    for (int ks = 0; ks < 8; ks++) {
        int k0 = ks * 16;
        int kp0 = ks * 8;
        uint32_t a[2][4];
#pragma unroll
        for (int mt = 0; mt < 2; mt++) {
            int rb = wm * 32 + mt * 16;
            a[mt][0] = *((const uint32_t*)&Us[(rb + gq) * US_HSTRIDE + k0 + 2 * tg]);
            a[mt][1] = *((const uint32_t*)&Us[(rb + gq + 8) * US_HSTRIDE + k0 + 2 * tg]);
            a[mt][2] = *((const uint32_t*)&Us[(rb + gq) * US_HSTRIDE + k0 + 2 * tg + 8]);
            a[mt][3] = *((const uint32_t*)&Us[(rb + gq + 8) * US_HSTRIDE + k0 + 2 * tg + 8]);
        }
        uint32_t b[8][2];
#pragma unroll
        for (int nt = 0; nt < 8; nt++) {
            int col = wn * 64 + nt * 8 + gq;
            b[nt][0] = Wp[(kp0 + tg) * WP_WSTRIDE + col];
            b[nt][1] = Wp[(kp0 + 4 + tg) * WP_WSTRIDE + col];
        }
#pragma unroll
        for (int mt = 0; mt < 2; mt++)
#pragma unroll
            for (int nt = 0; nt < 8; nt++) {
                asm volatile(
                    "mma.sync.aligned.m16n8k16.row.col.f32.f16.f16.f32 "
                    "{%0,%1,%2,%3}, {%4,%5,%6,%7}, {%8,%9}, {%0,%1,%2,%3};"
                    : "+f"(c[mt][nt][0]), "+f"(c[mt][nt][1]),
                      "+f"(c[mt][nt][2]), "+f"(c[mt][nt][3])
                    : "r"(a[mt][0]), "r"(a[mt][1]), "r"(a[mt][2]), "r"(a[mt][3]),
                      "r"(b[nt][0]), "r"(b[nt][1]));
            }
    }
}

// ================= fused per-layer MLP (fp16 HMMA) =================
__global__ __launch_bounds__(256, 2) void k_fused(
    int layer0, int last,
    const float* __restrict__ W1, const float* __restrict__ b1,
    const float* __restrict__ gam, const float* __restrict__ bet,
    const float* __restrict__ mu, const float* __restrict__ var,
    const float* __restrict__ W2, const float* __restrict__ b2,
    const int* __restrict__ batch, const float* __restrict__ Wc,
    float* __restrict__ out) {
    extern __shared__ char smem[];
    __half* Us = (__half*)smem;
    uint32_t* Wp = (uint32_t*)(smem + US_BYTES);
    float* Xf = (float*)(smem + US_BYTES);   // alias: layer0 params / rowdot

    int tid = threadIdx.x;
    int warp = tid >> 5, lane = tid & 31;
    int wm = warp & 3;
    int wn = warp >> 2;
    int gq = lane >> 2;
    int tg = lane & 3;
    int row0 = blockIdx.x * 128;

    // ================= stage 1 =================
    if (layer0) {
        float* W1s = Xf;
        float* sc = Xf + 384;
        float* sh = Xf + 512;
        for (int i = tid; i < 384; i += 256) W1s[i] = W1[i];
        if (tid < 128) {
            float s = gam[tid] * rsqrtf(var[tid] + BN_EPS);
            sc[tid] = s;
            sh[tid] = bet[tid] + (b1[tid] - mu[tid]) * s;
        }
        __syncthreads();
#pragma unroll 4
        for (int i = 0; i < 64; i++) {
            int idx = tid + i * 256;
            int r = idx >> 7, c = idx & 127;
            int row = row0 + r;
            float x0 = 0.f, x1 = 0.f, x2 = 0.f;
            if (row < NN) {
                x0 = g_t3[row * 3 + 0];
                x1 = g_t3[row * 3 + 1];
                x2 = g_t3[row * 3 + 2];
            }
            float u = x0 * W1s[c] + x1 * W1s[128 + c] + x2 * W1s[256 + c];
            u = fmaxf(u * sc[c] + sh[c], 0.f);
            Us[r * US_HSTRIDE + c] = __float2half(u);
        }
        __syncthreads();
    } else {
        // ---- stage-1 staging: A tile (fp16) + packed W1 ----
#pragma unroll
        for (int i = 0; i < 16; i++) {
            int idx = tid + i * 256;   // 4096 uint2 loads (4 halves each)
            int r = idx >> 5;
            int q = idx & 31;
            int row = row0 + r;
            uint2 v = make_uint2(0u, 0u);
            if (row < NN) v = *((const uint2*)&g_t[row * 128 + q * 4]);
            *((uint2*)&Us[r * US_HSTRIDE + q * 4]) = v;
        }
        pack_weights(Wp, W1, tid);
        __syncthreads();

        float c1[2][8][4];
#pragma unroll
        for (int mt = 0; mt < 2; mt++)
#pragma unroll
            for (int nt = 0; nt < 8; nt++)
#pragma unroll
                for (int r = 0; r < 4; r++) c1[mt][nt][r] = 0.f;

        mma_fullk(c1, Us, Wp, wm, wn, gq, tg);
        __syncthreads();   // all Us/Wp reads done before overwrite

        // BN + ReLU -> Us in place (fp16)
#pragma unroll
        for (int nt = 0; nt < 8; nt++) {
            int col = wn * 64 + nt * 8 + tg * 2;
            float s0 = gam[col] * rsqrtf(var[col] + BN_EPS);
            float s1 = gam[col + 1] * rsqrtf(var[col + 1] + BN_EPS);
            float sh0 = bet[col] + (b1[col] - mu[col]) * s0;
            float sh1 = bet[col + 1] + (b1[col + 1] - mu[col + 1]) * s1;
#pragma unroll
            for (int mt = 0; mt < 2; mt++) {
                int rb = wm * 32 + mt * 16 + gq;
#pragma unroll
                for (int half = 0; half < 2; half++) {
                    int r = rb + half * 8;
                    float v0 = fmaxf(c1[mt][nt][half * 2 + 0] * s0 + sh0, 0.f);
                    float v1 = fmaxf(c1[mt][nt][half * 2 + 1] * s1 + sh1, 0.f);
                    *((__half2*)&Us[r * US_HSTRIDE + col]) = __floats2half2_rn(v0, v1);
                }
            }
        }
        __syncthreads();
    }

    // ================= stage 2: h = ReLU(Us @ W2 + b2) =================
    pack_weights(Wp, W2, tid);   // overwrite W1 / layer0 params (post-sync)
    __syncthreads();

    float c2[2][8][4];
#pragma unroll
    for (int mt = 0; mt < 2; mt++)
#pragma unroll
        for (int nt = 0; nt < 8; nt++)
#pragma unroll
            for (int r = 0; r < 4; r++) c2[mt][nt][r] = 0.f;

    mma_fullk(c2, Us, Wp, wm, wn, gq, tg);

    if (!last) {
        // epilogue: bias + ReLU -> g_h (fp16)
#pragma unroll
        for (int nt = 0; nt < 8; nt++) {
            int col = wn * 64 + nt * 8 + tg * 2;
            float sh0 = b2[col];
            float sh1 = b2[col + 1];
#pragma unroll
            for (int mt = 0; mt < 2; mt++) {
                int r0 = row0 + wm * 32 + mt * 16 + gq;
#pragma unroll
                for (int half = 0; half < 2; half++) {
                    int row = r0 + half * 8;
                    if (row >= NN) continue;
                    float v0 = fmaxf(c2[mt][nt][half * 2 + 0] + sh0, 0.f);
                    float v1 = fmaxf(c2[mt][nt][half * 2 + 1] + sh1, 0.f);
                    *((__half2*)&g_h[row * 128 + col]) = __floats2half2_rn(v0, v1);
                }
            }
        }
    } else {
        // fused pool+classify; rowdot aliases Wp -> sync before reuse
        __syncthreads();
        float* rowdot = Xf;
        if (tid < 128) rowdot[tid] = 0.f;
        __syncthreads();
#pragma unroll
        for (int mt = 0; mt < 2; mt++) {
#pragma unroll
            for (int half = 0; half < 2; half++) {
                int r = wm * 32 + mt * 16 + gq + half * 8;
                if (row0 + r >= NN) continue;
                float p = 0.f;
#pragma unroll
                for (int nt = 0; nt < 8; nt++) {
                    int col = wn * 64 + nt * 8 + tg * 2;
                    float v0 = fmaxf(c2[mt][nt][half * 2 + 0] + b2[col], 0.f);
                    float v1 = fmaxf(c2[mt][nt][half * 2 + 1] + b2[col + 1], 0.f);
                    p += v0 * Wc[col] + v1 * Wc[col + 1];
                }
                atomicAdd(&rowdot[r], p);
            }
        }
        __syncthreads();
        if (tid < 128) {
            int row = row0 + tid;
            if (row < NN) atomicAdd(&out[batch[row]], rowdot[tid]);
        }
    }
}

extern "C" void kernel_launch(void* const* d_in, const int* in_sizes, int n_in,
                              void* d_out, int out_size) {
    const float* x    = (const float*)d_in[0];
    const int* ei     = (const int*)d_in[1];
    const int* batch  = (const int*)d_in[2];
    const float* W1_0 = (const float*)d_in[3];
    const float* b1_0 = (const float*)d_in[4];
    const float* g_0  = (const float*)d_in[5];
    const float* be_0 = (const float*)d_in[6];
    const float* m_0  = (const float*)d_in[7];
    const float* v_0  = (const float*)d_in[8];
    const float* W2_0 = (const float*)d_in[9];
    const float* b2_0 = (const float*)d_in[10];
    const float* W1s  = (const float*)d_in[11];
    const float* b1s  = (const float*)d_in[12];
    const float* gs   = (const float*)d_in[13];
    const float* bes  = (const float*)d_in[14];
    const float* ms   = (const float*)d_in[15];
    const float* vs   = (const float*)d_in[16];
    const float* W2s  = (const float*)d_in[17];
    const float* b2s  = (const float*)d_in[18];
    const float* Wc   = (const float*)d_in[19];
    const float* bc   = (const float*)d_in[20];
    float* out = (float*)d_out;

    cudaFuncSetAttribute(k_fused, cudaFuncAttributeMaxDynamicSharedMemorySize, SMEM_BYTES);

    const int T = 256;
    const int gemm_grid = (NN + 127) / 128;

    // ---- CSR build (dst-sorted adjacency) ----
    k_zero_deg<<<(NN + T - 1) / T, T>>>();
    k_hist<<<(EE + T - 1) / T, T>>>(ei);
    k_scan1<<<NB_SCAN, 1024>>>();
    k_scan2<<<1, 128>>>();
    k_scan3<<<(NN + T - 1) / T, T>>>();
    k_reorder<<<(EE + T - 1) / T, T>>>(ei);

    // ---- layer 0 (in=3) ----
    k_gather3<<<(NN + T - 1) / T, T>>>(x);
    k_init_out<<<(GG + T - 1) / T, T>>>(bc, out);
    k_fused<<<gemm_grid, 256, SMEM_BYTES>>>(1, 0, W1_0, b1_0, g_0, be_0, m_0, v_0,
                                            W2_0, b2_0, batch, Wc, out);

    // ---- layers 1..4 ----
    for (int l = 0; l < 4; l++) {
        int last = (l == 3) ? 1 : 0;
        k_gather<<<(NN + 7) / 8, 256>>>();
        k_fused<<<gemm_grid, 256, SMEM_BYTES>>>(0, last,
            W1s + l * HH * HH, b1s + l * HH,
            gs + l * HH, bes + l * HH, ms + l * HH, vs + l * HH,
            W2s + l * HH * HH, b2s + l * HH, batch, Wc, out);
    }
}

// round 12
// speedup vs baseline: 1.8290x; 1.0518x over previous
#include <cuda_runtime.h>
#include <cuda_fp16.h>
#include <cstdint>

#define NN 100000
#define EE 600000
#define HH 128
#define GG 1000
#define BN_EPS 1e-5f
#define NB_SCAN 98   // ceil(NN/1024)

// ---- scratch (alloc-free: __device__ globals) ----
__device__ __half g_t[NN * HH];    // h + agg (pre-MLP input), fp16
__device__ __half g_h[NN * HH];    // layer output features, fp16
__device__ float g_t3[NN * 3];     // layer-0 pre-MLP (3 feats)
__device__ uint32_t g_wp[9][64 * 128];  // pre-packed fp16 k-pair weights
// CSR scratch
__device__ int g_deg[NN];
__device__ int g_rowptr[NN + 1];
__device__ int g_cursor[NN];
__device__ int g_bsum[128];
__device__ int g_csr[EE];

// smem layout: Us (fp16 A / activations) + Wp (packed fp16 weights, k-pairs)
#define US_HSTRIDE 136                    // halves; word bank = 4r+tg (conflict-free)
#define US_BYTES (128 * US_HSTRIDE * 2)   // 34816
#define WP_WSTRIDE 132                    // words;  bank = 4tg+gq (conflict-free)
#define WP_BYTES (64 * WP_WSTRIDE * 4)    // 33792
#define SMEM_BYTES (US_BYTES + WP_BYTES)  // 68608

// ================= weight pre-pack =================
// m=0: W2_0; m=1..4: W1s[l]; m=5..8: W2s[l]. Wp[m][kp*128+col] = (W[2kp][col], W[2kp+1][col])
__global__ void k_pack(const float* __restrict__ W2_0, const float* __restrict__ W1s,
                       const float* __restrict__ W2s) {
    int idx = blockIdx.x * 256 + threadIdx.x;
    if (idx >= 9 * 8192) return;
    int m = idx >> 13;
    int w = idx & 8191;
    int kp = w >> 7;
    int col = w & 127;
    const float* W = (m == 0) ? W2_0 : (m <= 4 ? W1s + (m - 1) * 16384 : W2s + (m - 5) * 16384);
    __half2 h = __floats2half2_rn(W[(2 * kp) * 128 + col], W[(2 * kp + 1) * 128 + col]);
    g_wp[m][w] = *(uint32_t*)&h;
}

// ================= CSR build =================
__global__ void k_zero_deg() {
    int i = blockIdx.x * blockDim.x + threadIdx.x;
    if (i < NN) g_deg[i] = 0;
}

__global__ void k_hist(const int* __restrict__ ei) {
    int e = blockIdx.x * blockDim.x + threadIdx.x;
    if (e < EE) atomicAdd(&g_deg[ei[EE + e]], 1);
}

__global__ __launch_bounds__(1024) void k_scan1() {
    __shared__ int s[1024];
    int tid = threadIdx.x;
    int i = blockIdx.x * 1024 + tid;
    int v = (i < NN) ? g_deg[i] : 0;
    s[tid] = v;
    __syncthreads();
#pragma unroll
    for (int off = 1; off < 1024; off <<= 1) {
        int t = (tid >= off) ? s[tid - off] : 0;
        __syncthreads();
        s[tid] += t;
        __syncthreads();
    }
    if (i < NN) g_rowptr[i] = s[tid] - v;
    if (tid == 1023) g_bsum[blockIdx.x] = s[1023];
}

__global__ void k_scan2() {
    __shared__ int s[128];
    int tid = threadIdx.x;
    int v = (tid < NB_SCAN) ? g_bsum[tid] : 0;
    s[tid] = v;
    __syncthreads();
#pragma unroll
    for (int off = 1; off < 128; off <<= 1) {
        int t = (tid >= off) ? s[tid - off] : 0;
        __syncthreads();
        s[tid] += t;
        __syncthreads();
    }
    if (tid < NB_SCAN) g_bsum[tid] = s[tid] - v;
}

__global__ void k_scan3() {
    int i = blockIdx.x * blockDim.x + threadIdx.x;
    if (i < NN) {
        int r = g_rowptr[i] + g_bsum[i >> 10];
        g_rowptr[i] = r;
        g_cursor[i] = r;
    }
    if (i == 0) g_rowptr[NN] = EE;
}

__global__ void k_reorder(const int* __restrict__ ei) {
    int e = blockIdx.x * blockDim.x + threadIdx.x;
    if (e >= EE) return;
    int s = ei[e];
    int d = ei[EE + e];
    int pos = atomicAdd(&g_cursor[d], 1);
    g_csr[pos] = s;
}

// ================= gathers =================
__global__ void k_gather3(const float* __restrict__ x) {
    int n = blockIdx.x * blockDim.x + threadIdx.x;
    if (n >= NN) return;
    int beg = g_rowptr[n], end = g_rowptr[n + 1];
    float a0 = x[n * 3 + 0], a1 = x[n * 3 + 1], a2 = x[n * 3 + 2];
    for (int p = beg; p < end; p++) {
        int s = g_csr[p];
        a0 += x[s * 3 + 0];
        a1 += x[s * 3 + 1];
        a2 += x[s * 3 + 2];
    }
    g_t3[n * 3 + 0] = a0;
    g_t3[n * 3 + 1] = a1;
    g_t3[n * 3 + 2] = a2;
}

__device__ __forceinline__ void acc_half4(float4& acc, uint2 r) {
    float2 f0 = __half22float2(*(__half2*)&r.x);
    float2 f1 = __half22float2(*(__half2*)&r.y);
    acc.x += f0.x;
    acc.y += f0.y;
    acc.z += f1.x;
    acc.w += f1.y;
}

__global__ __launch_bounds__(256) void k_gather() {
    int n = blockIdx.x * 8 + (threadIdx.x >> 5);
    if (n >= NN) return;
    int lane = threadIdx.x & 31;
    int beg = g_rowptr[n], end = g_rowptr[n + 1];
    float4 acc = make_float4(0.f, 0.f, 0.f, 0.f);
    acc_half4(acc, *((const uint2*)&g_h[n * HH + lane * 4]));
    int p = beg;
    for (; p + 3 < end; p += 4) {
        int s0 = g_csr[p], s1 = g_csr[p + 1], s2 = g_csr[p + 2], s3 = g_csr[p + 3];
        uint2 v0 = *((const uint2*)&g_h[s0 * HH + lane * 4]);
        uint2 v1 = *((const uint2*)&g_h[s1 * HH + lane * 4]);
        uint2 v2 = *((const uint2*)&g_h[s2 * HH + lane * 4]);
        uint2 v3 = *((const uint2*)&g_h[s3 * HH + lane * 4]);
        acc_half4(acc, v0);
        acc_half4(acc, v1);
        acc_half4(acc, v2);
        acc_half4(acc, v3);
    }
    for (; p < end; p++) {
        acc_half4(acc, *((const uint2*)&g_h[g_csr[p] * HH + lane * 4]));
    }
    __half2 o0 = __floats2half2_rn(acc.x, acc.y);
    __half2 o1 = __floats2half2_rn(acc.z, acc.w);
    uint2 o;
    o.x = *(uint32_t*)&o0;
    o.y = *(uint32_t*)&o1;
    *((uint2*)&g_t[n * HH + lane * 4]) = o;
}

// ================= out init =================
__global__ void k_init_out(const float* __restrict__ bc, float* __restrict__ out) {
    int g = blockIdx.x * blockDim.x + threadIdx.x;
    if (g < GG) out[g] = bc[0];
}

// ================= helpers for k_fused =================
// copy pre-packed weights (gmem, dense [kp][col]) into padded smem
__device__ __forceinline__ void stage_weights(uint32_t* Wp, const uint32_t* __restrict__ src, int tid) {
#pragma unroll
    for (int i = 0; i < 8; i++) {
        int idx = tid + i * 256;      // uint4 idx 0..2047
        int kp = idx >> 5;
        int c4 = (idx & 31) * 4;
        uint4 v = *((const uint4*)&src[kp * 128 + c4]);
        *((uint4*)&Wp[kp * WP_WSTRIDE + c4]) = v;
    }
}

// ldmatrix.x4: A fragment (m16k16) for rows rb..rb+15, k-halves k0..k0+15
__device__ __forceinline__ void ldsm_a(uint32_t a[4], const __half* Us, int rb, int k0, int lane) {
    const __half* p = &Us[(rb + (lane & 15)) * US_HSTRIDE + k0 + ((lane >> 4) << 3)];
    uint32_t addr = (uint32_t)__cvta_generic_to_shared(p);
    asm volatile("ldmatrix.sync.aligned.m8n8.x4.shared.b16 {%0,%1,%2,%3}, [%4];"
                 : "=r"(a[0]), "=r"(a[1]), "=r"(a[2]), "=r"(a[3]) : "r"(addr));
}

// full-K (128) fp16 MMA: acc += Us(rows) @ Wp
__device__ __forceinline__ void mma_fullk(
    float c[2][8][4], const __half* Us, const uint32_t* Wp,
    int wm, int wn, int gq, int tg, int lane) {
#pragma unroll
    for (int ks = 0; ks < 8; ks++) {
        int k0 = ks * 16;
        int kp0 = ks * 8;
        uint32_t a[2][4];
        ldsm_a(a[0], Us, wm * 32, k0, lane);
        ldsm_a(a[1], Us, wm * 32 + 16, k0, lane);
        uint32_t b[8][2];
#pragma unroll
        for (int nt = 0; nt < 8; nt++) {
            int col = wn * 64 + nt * 8 + gq;
            b[nt][0] = Wp[(kp0 + tg) * WP_WSTRIDE + col];
            b[nt][1] = Wp[(kp0 + 4 + tg) * WP_WSTRIDE + col];
        }
#pragma unroll
        for (int mt = 0; mt < 2; mt++)
#pragma unroll
            for (int nt = 0; nt < 8; nt++) {
                asm volatile(
                    "mma.sync.aligned.m16n8k16.row.col.f32.f16.f16.f32 "
                    "{%0,%1,%2,%3}, {%4,%5,%6,%7}, {%8,%9}, {%0,%1,%2,%3};"
                    : "+f"(c[mt][nt][0]), "+f"(c[mt][nt][1]),
                      "+f"(c[mt][nt][2]), "+f"(c[mt][nt][3])
                    : "r"(a[mt][0]), "r"(a[mt][1]), "r"(a[mt][2]), "r"(a[mt][3]),
                      "r"(b[nt][0]), "r"(b[nt][1]));
            }
    }
}

// ================= fused per-layer MLP (fp16 HMMA, pre-packed weights) =================
__global__ __launch_bounds__(256, 2) void k_fused(
    int layer0, int last, int m1, int m2,
    const float* __restrict__ W1_0, const float* __restrict__ b1,
    const float* __restrict__ gam, const float* __restrict__ bet,
    const float* __restrict__ mu, const float* __restrict__ var,
    const float* __restrict__ b2,
    const int* __restrict__ batch, const float* __restrict__ Wc,
    float* __restrict__ out) {
    extern __shared__ char smem[];
    __half* Us = (__half*)smem;
    uint32_t* Wp = (uint32_t*)(smem + US_BYTES);
    float* Xf = (float*)(smem + US_BYTES);   // alias: layer0 params / rowdot

    int tid = threadIdx.x;
    int warp = tid >> 5, lane = tid & 31;
    int wm = warp & 3;
    int wn = warp >> 2;
    int gq = lane >> 2;
    int tg = lane & 3;
    int row0 = blockIdx.x * 128;

    // ================= stage 1 =================
    if (layer0) {
        float* W1s = Xf;          // 384
        float* sc = Xf + 384;     // 128
        float* sh = Xf + 512;     // 128
        float* t3s = Xf + 640;    // 384 (tile's 3-feat inputs)
        for (int i = tid; i < 384; i += 256) {
            W1s[i] = W1_0[i];
            int gi = row0 * 3 + i;
            t3s[i] = (gi < NN * 3) ? g_t3[gi] : 0.f;
        }
        if (tid < 128) {
            float s = gam[tid] * rsqrtf(var[tid] + BN_EPS);
            sc[tid] = s;
            sh[tid] = bet[tid] + (b1[tid] - mu[tid]) * s;
        }
        __syncthreads();
#pragma unroll 4
        for (int i = 0; i < 64; i++) {
            int idx = tid + i * 256;
            int r = idx >> 7, c = idx & 127;
            float x0 = t3s[r * 3 + 0];   // warp-broadcast LDS
            float x1 = t3s[r * 3 + 1];
            float x2 = t3s[r * 3 + 2];
            float u = x0 * W1s[c] + x1 * W1s[128 + c] + x2 * W1s[256 + c];
            u = fmaxf(u * sc[c] + sh[c], 0.f);
            Us[r * US_HSTRIDE + c] = __float2half(u);
        }
        __syncthreads();
    } else {
        // ---- stage-1 staging: A tile (fp16, uint4) + packed W1 ----
#pragma unroll
        for (int i = 0; i < 8; i++) {
            int idx = tid + i * 256;   // 2048 uint4 loads (8 halves each)
            int r = idx >> 4;
            int q = idx & 15;
            int row = row0 + r;
            uint4 v = make_uint4(0u, 0u, 0u, 0u);
            if (row < NN) v = *((const uint4*)&g_t[row * 128 + q * 8]);
            *((uint4*)&Us[r * US_HSTRIDE + q * 8]) = v;
        }
        stage_weights(Wp, g_wp[m1], tid);
        __syncthreads();

        float c1[2][8][4];
#pragma unroll
        for (int mt = 0; mt < 2; mt++)
#pragma unroll
            for (int nt = 0; nt < 8; nt++)
#pragma unroll
                for (int r = 0; r < 4; r++) c1[mt][nt][r] = 0.f;

        mma_fullk(c1, Us, Wp, wm, wn, gq, tg, lane);
        __syncthreads();   // all Us/Wp reads done before overwrite

        // BN + ReLU -> Us in place (fp16)
#pragma unroll
        for (int nt = 0; nt < 8; nt++) {
            int col = wn * 64 + nt * 8 + tg * 2;
            float s0 = gam[col] * rsqrtf(var[col] + BN_EPS);
            float s1 = gam[col + 1] * rsqrtf(var[col + 1] + BN_EPS);
            float sh0 = bet[col] + (b1[col] - mu[col]) * s0;
            float sh1 = bet[col + 1] + (b1[col + 1] - mu[col + 1]) * s1;
#pragma unroll
            for (int mt = 0; mt < 2; mt++) {
                int rb = wm * 32 + mt * 16 + gq;
#pragma unroll
                for (int half = 0; half < 2; half++) {
                    int r = rb + half * 8;
                    float v0 = fmaxf(c1[mt][nt][half * 2 + 0] * s0 + sh0, 0.f);
                    float v1 = fmaxf(c1[mt][nt][half * 2 + 1] * s1 + sh1, 0.f);
                    *((__half2*)&Us[r * US_HSTRIDE + col]) = __floats2half2_rn(v0, v1);
                }
            }
        }
        __syncthreads();
    }

    // ================= stage 2: h = ReLU(Us @ W2 + b2) =================
    stage_weights(Wp, g_wp[m2], tid);   // overwrite W1 / layer0 params (post-sync)
    __syncthreads();

    float c2[2][8][4];
#pragma unroll
    for (int mt = 0; mt < 2; mt++)
#pragma unroll
        for (int nt = 0; nt < 8; nt++)
#pragma unroll
            for (int r = 0; r < 4; r++) c2[mt][nt][r] = 0.f;

    mma_fullk(c2, Us, Wp, wm, wn, gq, tg, lane);

    if (!last) {
        // epilogue: bias + ReLU -> g_h (fp16)
#pragma unroll
        for (int nt = 0; nt < 8; nt++) {
            int col = wn * 64 + nt * 8 + tg * 2;
            float sh0 = b2[col];
            float sh1 = b2[col + 1];
#pragma unroll
            for (int mt = 0; mt < 2; mt++) {
                int r0 = row0 + wm * 32 + mt * 16 + gq;
#pragma unroll
                for (int half = 0; half < 2; half++) {
                    int row = r0 + half * 8;
                    if (row >= NN) continue;
                    float v0 = fmaxf(c2[mt][nt][half * 2 + 0] + sh0, 0.f);
                    float v1 = fmaxf(c2[mt][nt][half * 2 + 1] + sh1, 0.f);
                    *((__half2*)&g_h[row * 128 + col]) = __floats2half2_rn(v0, v1);
                }
            }
        }
    } else {
        // fused pool+classify; rowdot aliases Wp -> sync before reuse
        __syncthreads();
        float* rowdot = Xf;
        if (tid < 128) rowdot[tid] = 0.f;
        __syncthreads();
#pragma unroll
        for (int mt = 0; mt < 2; mt++) {
#pragma unroll
            for (int half = 0; half < 2; half++) {
                int r = wm * 32 + mt * 16 + gq + half * 8;
                if (row0 + r >= NN) continue;
                float p = 0.f;
#pragma unroll
                for (int nt = 0; nt < 8; nt++) {
                    int col = wn * 64 + nt * 8 + tg * 2;
                    float v0 = fmaxf(c2[mt][nt][half * 2 + 0] + b2[col], 0.f);
                    float v1 = fmaxf(c2[mt][nt][half * 2 + 1] + b2[col + 1], 0.f);
                    p += v0 * Wc[col] + v1 * Wc[col + 1];
                }
                atomicAdd(&rowdot[r], p);
            }
        }
        __syncthreads();
        if (tid < 128) {
            int row = row0 + tid;
            if (row < NN) atomicAdd(&out[batch[row]], rowdot[tid]);
        }
    }
}

extern "C" void kernel_launch(void* const* d_in, const int* in_sizes, int n_in,
                              void* d_out, int out_size) {
    const float* x    = (const float*)d_in[0];
    const int* ei     = (const int*)d_in[1];
    const int* batch  = (const int*)d_in[2];
    const float* W1_0 = (const float*)d_in[3];
    const float* b1_0 = (const float*)d_in[4];
    const float* g_0  = (const float*)d_in[5];
    const float* be_0 = (const float*)d_in[6];
    const float* m_0  = (const float*)d_in[7];
    const float* v_0  = (const float*)d_in[8];
    const float* W2_0 = (const float*)d_in[9];
    const float* b2_0 = (const float*)d_in[10];
    const float* W1s  = (const float*)d_in[11];
    const float* b1s  = (const float*)d_in[12];
    const float* gs   = (const float*)d_in[13];
    const float* bes  = (const float*)d_in[14];
    const float* ms   = (const float*)d_in[15];
    const float* vs   = (const float*)d_in[16];
    const float* W2s  = (const float*)d_in[17];
    const float* b2s  = (const float*)d_in[18];
    const float* Wc   = (const float*)d_in[19];
    const float* bc   = (const float*)d_in[20];
    float* out = (float*)d_out;

    cudaFuncSetAttribute(k_fused, cudaFuncAttributeMaxDynamicSharedMemorySize, SMEM_BYTES);

    const int T = 256;
    const int gemm_grid = (NN + 127) / 128;

    // ---- weight pre-pack + CSR build ----
    k_pack<<<(9 * 8192 + T - 1) / T, T>>>(W2_0, W1s, W2s);
    k_zero_deg<<<(NN + T - 1) / T, T>>>();
    k_hist<<<(EE + T - 1) / T, T>>>(ei);
    k_scan1<<<NB_SCAN, 1024>>>();
    k_scan2<<<1, 128>>>();
    k_scan3<<<(NN + T - 1) / T, T>>>();
    k_reorder<<<(EE + T - 1) / T, T>>>(ei);

    // ---- layer 0 (in=3) ----
    k_gather3<<<(NN + T - 1) / T, T>>>(x);
    k_init_out<<<(GG + T - 1) / T, T>>>(bc, out);
    k_fused<<<gemm_grid, 256, SMEM_BYTES>>>(1, 0, 0, 0, W1_0, b1_0, g_0, be_0, m_0, v_0,
                                            b2_0, batch, Wc, out);

    // ---- layers 1..4 ----
    for (int l = 0; l < 4; l++) {
        int last = (l == 3) ? 1 : 0;
        k_gather<<<(NN + 7) / 8, 256>>>();
        k_fused<<<gemm_grid, 256, SMEM_BYTES>>>(0, last, 1 + l, 5 + l,
            W1_0, b1s + l * HH,
            gs + l * HH, bes + l * HH, ms + l * HH, vs + l * HH,
            b2s + l * HH, batch, Wc, out);
    }
}

// round 13
// speedup vs baseline: 1.8499x; 1.0114x over previous
#include <cuda_runtime.h>
#include <cuda_fp16.h>
#include <cstdint>

#define NN 100000
#define EE 600000
#define HH 128
#define GG 1000
#define BN_EPS 1e-5f
#define NB_SCAN 98   // ceil(NN/1024)

// ---- scratch (alloc-free: __device__ globals) ----
__device__ __half g_t[NN * HH];    // h + agg (pre-MLP input), fp16
__device__ __half g_h[NN * HH];    // layer output features, fp16
__device__ float g_t3[NN * 3];     // layer-0 pre-MLP (3 feats)
__device__ uint32_t g_wp[9][64 * 128];  // pre-packed fp16 k-pair weights
// CSR scratch
__device__ int g_deg[NN];
__device__ int g_rowptr[NN + 1];
__device__ int g_cursor[NN];
__device__ int g_bsum[128];
__device__ int g_csr[EE];

// smem layout: Us (fp16 A/activations) + WpA (W1) + WpB (W2)
#define US_HSTRIDE 136                    // halves; conflict-free
#define US_BYTES (128 * US_HSTRIDE * 2)   // 34816
#define WP_WSTRIDE 132                    // words; conflict-free
#define WP_BYTES (64 * WP_WSTRIDE * 4)    // 33792
#define SMEM_BYTES (US_BYTES + 2 * WP_BYTES)  // 102400

__device__ __forceinline__ void cp_async16(uint32_t saddr, const void* gaddr, int szfill) {
    asm volatile("cp.async.ca.shared.global [%0], [%1], 16, %2;"
                 :: "r"(saddr), "l"(gaddr), "r"(szfill) : "memory");
}
__device__ __forceinline__ void cp_commit() {
    asm volatile("cp.async.commit_group;" ::: "memory");
}
template <int N>
__device__ __forceinline__ void cp_wait() {
    asm volatile("cp.async.wait_group %0;" :: "n"(N) : "memory");
}

// ================= weight pre-pack =================
__global__ void k_pack(const float* __restrict__ W2_0, const float* __restrict__ W1s,
                       const float* __restrict__ W2s) {
    int idx = blockIdx.x * 256 + threadIdx.x;
    if (idx >= 9 * 8192) return;
    int m = idx >> 13;
    int w = idx & 8191;
    int kp = w >> 7;
    int col = w & 127;
    const float* W = (m == 0) ? W2_0 : (m <= 4 ? W1s + (m - 1) * 16384 : W2s + (m - 5) * 16384);
    __half2 h = __floats2half2_rn(W[(2 * kp) * 128 + col], W[(2 * kp + 1) * 128 + col]);
    g_wp[m][w] = *(uint32_t*)&h;
}

// ================= CSR build =================
__global__ void k_zero_deg() {
    int i = blockIdx.x * blockDim.x + threadIdx.x;
    if (i < NN) g_deg[i] = 0;
}

__global__ void k_hist(const int* __restrict__ ei) {
    int e = blockIdx.x * blockDim.x + threadIdx.x;
    if (e < EE) atomicAdd(&g_deg[ei[EE + e]], 1);
}

__global__ __launch_bounds__(1024) void k_scan1() {
    __shared__ int s[1024];
    int tid = threadIdx.x;
    int i = blockIdx.x * 1024 + tid;
    int v = (i < NN) ? g_deg[i] : 0;
    s[tid] = v;
    __syncthreads();
#pragma unroll
    for (int off = 1; off < 1024; off <<= 1) {
        int t = (tid >= off) ? s[tid - off] : 0;
        __syncthreads();
        s[tid] += t;
        __syncthreads();
    }
    if (i < NN) g_rowptr[i] = s[tid] - v;
    if (tid == 1023) g_bsum[blockIdx.x] = s[1023];
}

__global__ void k_scan2() {
    __shared__ int s[128];
    int tid = threadIdx.x;
    int v = (tid < NB_SCAN) ? g_bsum[tid] : 0;
    s[tid] = v;
    __syncthreads();
#pragma unroll
    for (int off = 1; off < 128; off <<= 1) {
        int t = (tid >= off) ? s[tid - off] : 0;
        __syncthreads();
        s[tid] += t;
        __syncthreads();
    }
    if (tid < NB_SCAN) g_bsum[tid] = s[tid] - v;
}

__global__ void k_scan3() {
    int i = blockIdx.x * blockDim.x + threadIdx.x;
    if (i < NN) {
        int r = g_rowptr[i] + g_bsum[i >> 10];
        g_rowptr[i] = r;
        g_cursor[i] = r;
    }
    if (i == 0) g_rowptr[NN] = EE;
}

__global__ void k_reorder(const int* __restrict__ ei) {
    int e = blockIdx.x * blockDim.x + threadIdx.x;
    if (e >= EE) return;
    int s = ei[e];
    int d = ei[EE + e];
    int pos = atomicAdd(&g_cursor[d], 1);
    g_csr[pos] = s;
}

// ================= gathers =================
__global__ void k_gather3(const float* __restrict__ x) {
    int n = blockIdx.x * blockDim.x + threadIdx.x;
    if (n >= NN) return;
    int beg = g_rowptr[n], end = g_rowptr[n + 1];
    float a0 = x[n * 3 + 0], a1 = x[n * 3 + 1], a2 = x[n * 3 + 2];
    for (int p = beg; p < end; p++) {
        int s = g_csr[p];
        a0 += x[s * 3 + 0];
        a1 += x[s * 3 + 1];
        a2 += x[s * 3 + 2];
    }
    g_t3[n * 3 + 0] = a0;
    g_t3[n * 3 + 1] = a1;
    g_t3[n * 3 + 2] = a2;
}

__device__ __forceinline__ void acc_half4(float4& acc, uint2 r) {
    float2 f0 = __half22float2(*(__half2*)&r.x);
    float2 f1 = __half22float2(*(__half2*)&r.y);
    acc.x += f0.x;
    acc.y += f0.y;
    acc.z += f1.x;
    acc.w += f1.y;
}

__global__ __launch_bounds__(256) void k_gather() {
    int n = blockIdx.x * 8 + (threadIdx.x >> 5);
    if (n >= NN) return;
    int lane = threadIdx.x & 31;
    int beg = g_rowptr[n], end = g_rowptr[n + 1];
    float4 acc = make_float4(0.f, 0.f, 0.f, 0.f);
    acc_half4(acc, *((const uint2*)&g_h[n * HH + lane * 4]));
    int p = beg;
    for (; p + 3 < end; p += 4) {
        int s0 = g_csr[p], s1 = g_csr[p + 1], s2 = g_csr[p + 2], s3 = g_csr[p + 3];
        uint2 v0 = *((const uint2*)&g_h[s0 * HH + lane * 4]);
        uint2 v1 = *((const uint2*)&g_h[s1 * HH + lane * 4]);
        uint2 v2 = *((const uint2*)&g_h[s2 * HH + lane * 4]);
        uint2 v3 = *((const uint2*)&g_h[s3 * HH + lane * 4]);
        acc_half4(acc, v0);
        acc_half4(acc, v1);
        acc_half4(acc, v2);
        acc_half4(acc, v3);
    }
    for (; p < end; p++) {
        acc_half4(acc, *((const uint2*)&g_h[g_csr[p] * HH + lane * 4]));
    }
    __half2 o0 = __floats2half2_rn(acc.x, acc.y);
    __half2 o1 = __floats2half2_rn(acc.z, acc.w);
    uint2 o;
    o.x = *(uint32_t*)&o0;
    o.y = *(uint32_t*)&o1;
    *((uint2*)&g_t[n * HH + lane * 4]) = o;
}

// ================= out init =================
__global__ void k_init_out(const float* __restrict__ bc, float* __restrict__ out) {
    int g = blockIdx.x * blockDim.x + threadIdx.x;
    if (g < GG) out[g] = bc[0];
}

// ================= helpers for k_fused =================
// cp.async stage of pre-packed weights into padded smem
__device__ __forceinline__ void stage_weights_async(uint32_t wp_s, const uint32_t* __restrict__ src, int tid) {
#pragma unroll
    for (int i = 0; i < 8; i++) {
        int idx = tid + i * 256;      // uint4 idx 0..2047
        int kp = idx >> 5;
        int c4 = (idx & 31) * 4;
        cp_async16(wp_s + (kp * WP_WSTRIDE + c4) * 4, &src[kp * 128 + c4], 16);
    }
}

// ldmatrix.x4: A fragment (m16k16)
__device__ __forceinline__ void ldsm_a(uint32_t a[4], const __half* Us, int rb, int k0, int lane) {
    const __half* p = &Us[(rb + (lane & 15)) * US_HSTRIDE + k0 + ((lane >> 4) << 3)];
    uint32_t addr = (uint32_t)__cvta_generic_to_shared(p);
    asm volatile("ldmatrix.sync.aligned.m8n8.x4.shared.b16 {%0,%1,%2,%3}, [%4];"
                 : "=r"(a[0]), "=r"(a[1]), "=r"(a[2]), "=r"(a[3]) : "r"(addr));
}

// full-K (128) fp16 MMA
__device__ __forceinline__ void mma_fullk(
    float c[2][8][4], const __half* Us, const uint32_t* Wp,
    int wm, int wn, int gq, int tg, int lane) {
#pragma unroll
    for (int ks = 0; ks < 8; ks++) {
        int k0 = ks * 16;
        int kp0 = ks * 8;
        uint32_t a[2][4];
        ldsm_a(a[0], Us, wm * 32, k0, lane);
        ldsm_a(a[1], Us, wm * 32 + 16, k0, lane);
        uint32_t b[8][2];
#pragma unroll
        for (int nt = 0; nt < 8; nt++) {
            int col = wn * 64 + nt * 8 + gq;
            b[nt][0] = Wp[(kp0 + tg) * WP_WSTRIDE + col];
            b[nt][1] = Wp[(kp0 + 4 + tg) * WP_WSTRIDE + col];
        }
#pragma unroll
        for (int mt = 0; mt < 2; mt++)
#pragma unroll
            for (int nt = 0; nt < 8; nt++) {
                asm volatile(
                    "mma.sync.aligned.m16n8k16.row.col.f32.f16.f16.f32 "
                    "{%0,%1,%2,%3}, {%4,%5,%6,%7}, {%8,%9}, {%0,%1,%2,%3};"
                    : "+f"(c[mt][nt][0]), "+f"(c[mt][nt][1]),
                      "+f"(c[mt][nt][2]), "+f"(c[mt][nt][3])
                    : "r"(a[mt][0]), "r"(a[mt][1]), "r"(a[mt][2]), "r"(a[mt][3]),
                      "r"(b[nt][0]), "r"(b[nt][1]));
            }
    }
}

// ================= fused per-layer MLP (cp.async triple-buffer) =================
__global__ __launch_bounds__(256, 2) void k_fused(
    int layer0, int last, int m1, int m2,
    const float* __restrict__ W1_0, const float* __restrict__ b1,
    const float* __restrict__ gam, const float* __restrict__ bet,
    const float* __restrict__ mu, const float* __restrict__ var,
    const float* __restrict__ b2,
    const int* __restrict__ batch, const float* __restrict__ Wc,
    float* __restrict__ out) {
    extern __shared__ char smem[];
    __half* Us = (__half*)smem;
    uint32_t* WpA = (uint32_t*)(smem + US_BYTES);
    uint32_t* WpB = (uint32_t*)(smem + US_BYTES + WP_BYTES);
    float* Xf = (float*)(smem + US_BYTES);   // alias WpA: layer0 params / rowdot
    uint32_t us_s = (uint32_t)__cvta_generic_to_shared(Us);
    uint32_t wpa_s = (uint32_t)__cvta_generic_to_shared(WpA);
    uint32_t wpb_s = (uint32_t)__cvta_generic_to_shared(WpB);

    int tid = threadIdx.x;
    int warp = tid >> 5, lane = tid & 31;
    int wm = warp & 3;
    int wn = warp >> 2;
    int gq = lane >> 2;
    int tg = lane & 3;
    int row0 = blockIdx.x * 128;

    // ================= stage 1 =================
    if (layer0) {
        // prefetch W2 (group0) while doing the ALU mini-MLP
        stage_weights_async(wpb_s, g_wp[m2], tid);
        cp_commit();

        float* W1s = Xf;          // 384
        float* sc = Xf + 384;     // 128
        float* sh = Xf + 512;     // 128
        float* t3s = Xf + 640;    // 384
        for (int i = tid; i < 384; i += 256) {
            W1s[i] = W1_0[i];
            int gi = row0 * 3 + i;
            t3s[i] = (gi < NN * 3) ? g_t3[gi] : 0.f;
        }
        if (tid < 128) {
            float s = gam[tid] * rsqrtf(var[tid] + BN_EPS);
            sc[tid] = s;
            sh[tid] = bet[tid] + (b1[tid] - mu[tid]) * s;
        }
        __syncthreads();
#pragma unroll 4
        for (int i = 0; i < 64; i++) {
            int idx = tid + i * 256;
            int r = idx >> 7, c = idx & 127;
            float x0 = t3s[r * 3 + 0];
            float x1 = t3s[r * 3 + 1];
            float x2 = t3s[r * 3 + 2];
            float u = x0 * W1s[c] + x1 * W1s[128 + c] + x2 * W1s[256 + c];
            u = fmaxf(u * sc[c] + sh[c], 0.f);
            Us[r * US_HSTRIDE + c] = __float2half(u);
        }
        cp_wait<0>();
        __syncthreads();
    } else {
        // group0: A tile + W1; group1: W2
#pragma unroll
        for (int i = 0; i < 8; i++) {
            int idx = tid + i * 256;   // 2048 × 16B
            int r = idx >> 4;
            int q = idx & 15;
            int row = row0 + r;
            cp_async16(us_s + (r * US_HSTRIDE + q * 8) * 2,
                       &g_t[row * 128 + q * 8], (row < NN) ? 16 : 0);
        }
        stage_weights_async(wpa_s, g_wp[m1], tid);
        cp_commit();
        stage_weights_async(wpb_s, g_wp[m2], tid);
        cp_commit();

        cp_wait<1>();   // A + W1 ready; W2 still in flight
        __syncthreads();

        float c1[2][8][4];
#pragma unroll
        for (int mt = 0; mt < 2; mt++)
#pragma unroll
            for (int nt = 0; nt < 8; nt++)
#pragma unroll
                for (int r = 0; r < 4; r++) c1[mt][nt][r] = 0.f;

        mma_fullk(c1, Us, WpA, wm, wn, gq, tg, lane);
        cp_wait<0>();      // W2 arrived (overlapped with MMA)
        __syncthreads();   // Us reads done before overwrite; W2 visible after

        // BN + ReLU -> Us in place (fp16)
#pragma unroll
        for (int nt = 0; nt < 8; nt++) {
            int col = wn * 64 + nt * 8 + tg * 2;
            float s0 = gam[col] * rsqrtf(var[col] + BN_EPS);
            float s1 = gam[col + 1] * rsqrtf(var[col + 1] + BN_EPS);
            float sh0 = bet[col] + (b1[col] - mu[col]) * s0;
            float sh1 = bet[col + 1] + (b1[col + 1] - mu[col + 1]) * s1;
#pragma unroll
            for (int mt = 0; mt < 2; mt++) {
                int rb = wm * 32 + mt * 16 + gq;
#pragma unroll
                for (int half = 0; half < 2; half++) {
                    int r = rb + half * 8;
                    float v0 = fmaxf(c1[mt][nt][half * 2 + 0] * s0 + sh0, 0.f);
                    float v1 = fmaxf(c1[mt][nt][half * 2 + 1] * s1 + sh1, 0.f);
                    *((__half2*)&Us[r * US_HSTRIDE + col]) = __floats2half2_rn(v0, v1);
                }
            }
        }
        __syncthreads();
    }

    // ================= stage 2: h = ReLU(Us @ W2 + b2) =================
    float c2[2][8][4];
#pragma unroll
    for (int mt = 0; mt < 2; mt++)
#pragma unroll
        for (int nt = 0; nt < 8; nt++)
#pragma unroll
            for (int r = 0; r < 4; r++) c2[mt][nt][r] = 0.f;

    mma_fullk(c2, Us, WpB, wm, wn, gq, tg, lane);

    if (!last) {
        // epilogue: bias + ReLU -> g_h (fp16)
#pragma unroll
        for (int nt = 0; nt < 8; nt++) {
            int col = wn * 64 + nt * 8 + tg * 2;
            float sh0 = b2[col];
            float sh1 = b2[col + 1];
#pragma unroll
            for (int mt = 0; mt < 2; mt++) {
                int r0 = row0 + wm * 32 + mt * 16 + gq;
#pragma unroll
                for (int half = 0; half < 2; half++) {
                    int row = r0 + half * 8;
                    if (row >= NN) continue;
                    float v0 = fmaxf(c2[mt][nt][half * 2 + 0] + sh0, 0.f);
                    float v1 = fmaxf(c2[mt][nt][half * 2 + 1] + sh1, 0.f);
                    *((__half2*)&g_h[row * 128 + col]) = __floats2half2_rn(v0, v1);
                }
            }
        }
    } else {
        // fused pool+classify; rowdot aliases WpA -> sync before reuse
        __syncthreads();
        float* rowdot = Xf;
        if (tid < 128) rowdot[tid] = 0.f;
        __syncthreads();
#pragma unroll
        for (int mt = 0; mt < 2; mt++) {
#pragma unroll
            for (int half = 0; half < 2; half++) {
                int r = wm * 32 + mt * 16 + gq + half * 8;
                if (row0 + r >= NN) continue;
                float p = 0.f;
#pragma unroll
                for (int nt = 0; nt < 8; nt++) {
                    int col = wn * 64 + nt * 8 + tg * 2;
                    float v0 = fmaxf(c2[mt][nt][half * 2 + 0] + b2[col], 0.f);
                    float v1 = fmaxf(c2[mt][nt][half * 2 + 1] + b2[col + 1], 0.f);
                    p += v0 * Wc[col] + v1 * Wc[col + 1];
                }
                atomicAdd(&rowdot[r], p);
            }
        }
        __syncthreads();
        if (tid < 128) {
            int row = row0 + tid;
            if (row < NN) atomicAdd(&out[batch[row]], rowdot[tid]);
        }
    }
}

extern "C" void kernel_launch(void* const* d_in, const int* in_sizes, int n_in,
                              void* d_out, int out_size) {
    const float* x    = (const float*)d_in[0];
    const int* ei     = (const int*)d_in[1];
    const int* batch  = (const int*)d_in[2];
    const float* W1_0 = (const float*)d_in[3];
    const float* b1_0 = (const float*)d_in[4];
    const float* g_0  = (const float*)d_in[5];
    const float* be_0 = (const float*)d_in[6];
    const float* m_0  = (const float*)d_in[7];
    const float* v_0  = (const float*)d_in[8];
    const float* W2_0 = (const float*)d_in[9];
    const float* b2_0 = (const float*)d_in[10];
    const float* W1s  = (const float*)d_in[11];
    const float* b1s  = (const float*)d_in[12];
    const float* gs   = (const float*)d_in[13];
    const float* bes  = (const float*)d_in[14];
    const float* ms   = (const float*)d_in[15];
    const float* vs   = (const float*)d_in[16];
    const float* W2s  = (const float*)d_in[17];
    const float* b2s  = (const float*)d_in[18];
    const float* Wc   = (const float*)d_in[19];
    const float* bc   = (const float*)d_in[20];
    float* out = (float*)d_out;

    cudaFuncSetAttribute(k_fused, cudaFuncAttributeMaxDynamicSharedMemorySize, SMEM_BYTES);

    const int T = 256;
    const int gemm_grid = (NN + 127) / 128;

    // ---- weight pre-pack + CSR build ----
    k_pack<<<(9 * 8192 + T - 1) / T, T>>>(W2_0, W1s, W2s);
    k_zero_deg<<<(NN + T - 1) / T, T>>>();
    k_hist<<<(EE + T - 1) / T, T>>>(ei);
    k_scan1<<<NB_SCAN, 1024>>>();
    k_scan2<<<1, 128>>>();
    k_scan3<<<(NN + T - 1) / T, T>>>();
    k_reorder<<<(EE + T - 1) / T, T>>>(ei);

    // ---- layer 0 (in=3) ----
    k_gather3<<<(NN + T - 1) / T, T>>>(x);
    k_init_out<<<(GG + T - 1) / T, T>>>(bc, out);
    k_fused<<<gemm_grid, 256, SMEM_BYTES>>>(1, 0, 0, 0, W1_0, b1_0, g_0, be_0, m_0, v_0,
                                            b2_0, batch, Wc, out);

    // ---- layers 1..4 ----
    for (int l = 0; l < 4; l++) {
        int last = (l == 3) ? 1 : 0;
        k_gather<<<(NN + 7) / 8, 256>>>();
        k_fused<<<gemm_grid, 256, SMEM_BYTES>>>(0, last, 1 + l, 5 + l,
            W1_0, b1s + l * HH,
            gs + l * HH, bes + l * HH, ms + l * HH, vs + l * HH,
            b2s + l * HH, batch, Wc, out);
    }
}